// round 1
// baseline (speedup 1.0000x reference)
#include <cuda_runtime.h>
#include <cuda_bf16.h>
#include <math.h>

// Problem constants
#define BATCH   2
#define SEQ     2048
#define EMB     1024
#define NHEAD   16
#define HDIM    64
#define MROWS   (BATCH * SEQ)          // 4096
#define QKV_ELEMS (BATCH * NHEAD * SEQ * HDIM)   // 4,194,304

// Scratch (allocation-free rule: __device__ globals)
__device__ float g_Q[QKV_ELEMS];
__device__ float g_K[QKV_ELEMS];
__device__ float g_V[QKV_ELEMS];
__device__ float g_attn[MROWS * EMB];

// ---------------------------------------------------------------------------
// Tiled fp32 GEMM: C[m,n] = sum_k A[m,k] * W[n,k] + bias[n]
// M=4096, N=1024, K=1024 fixed.
// mode 0: write C in [B,H,S,D] layout (for Q/K/V)
// mode 1: write C row-major [M,N]
// ---------------------------------------------------------------------------
__global__ void __launch_bounds__(256)
gemm_bias_kernel(const float* __restrict__ A, const float* __restrict__ W,
                 const float* __restrict__ bias, float* __restrict__ C, int mode)
{
    const int K = 1024;
    __shared__ float As[16][128];
    __shared__ float Bs[16][128];

    const int tid  = threadIdx.x;
    const int bm   = blockIdx.y;    // 0..31
    const int bn   = blockIdx.x;    // 0..7

    const int rl  = tid >> 1;             // 0..127  (row within tile)
    const int kl  = (tid & 1) * 8;        // 0 or 8

    const float* Ag = A + (size_t)(bm * 128 + rl) * K + kl;
    const float* Wg = W + (size_t)(bn * 128 + rl) * K + kl;

    const int trow = tid >> 4;   // 0..15
    const int tcol = tid & 15;   // 0..15

    float acc[8][8];
#pragma unroll
    for (int i = 0; i < 8; i++)
#pragma unroll
        for (int j = 0; j < 8; j++) acc[i][j] = 0.f;

    for (int k0 = 0; k0 < K; k0 += 16) {
        float4 a0 = *(const float4*)(Ag + k0);
        float4 a1 = *(const float4*)(Ag + k0 + 4);
        float4 b0 = *(const float4*)(Wg + k0);
        float4 b1 = *(const float4*)(Wg + k0 + 4);

        __syncthreads();
        As[kl + 0][rl] = a0.x; As[kl + 1][rl] = a0.y;
        As[kl + 2][rl] = a0.z; As[kl + 3][rl] = a0.w;
        As[kl + 4][rl] = a1.x; As[kl + 5][rl] = a1.y;
        As[kl + 6][rl] = a1.z; As[kl + 7][rl] = a1.w;
        Bs[kl + 0][rl] = b0.x; Bs[kl + 1][rl] = b0.y;
        Bs[kl + 2][rl] = b0.z; Bs[kl + 3][rl] = b0.w;
        Bs[kl + 4][rl] = b1.x; Bs[kl + 5][rl] = b1.y;
        Bs[kl + 6][rl] = b1.z; Bs[kl + 7][rl] = b1.w;
        __syncthreads();

#pragma unroll
        for (int kk = 0; kk < 16; kk++) {
            float4 av0 = *(const float4*)&As[kk][trow * 8];
            float4 av1 = *(const float4*)&As[kk][trow * 8 + 4];
            float4 bv0 = *(const float4*)&Bs[kk][tcol * 8];
            float4 bv1 = *(const float4*)&Bs[kk][tcol * 8 + 4];
            float a[8] = {av0.x, av0.y, av0.z, av0.w, av1.x, av1.y, av1.z, av1.w};
            float b[8] = {bv0.x, bv0.y, bv0.z, bv0.w, bv1.x, bv1.y, bv1.z, bv1.w};
#pragma unroll
            for (int i = 0; i < 8; i++)
#pragma unroll
                for (int j = 0; j < 8; j++)
                    acc[i][j] = fmaf(a[i], b[j], acc[i][j]);
        }
    }

#pragma unroll
    for (int i = 0; i < 8; i++) {
        const int m = bm * 128 + trow * 8 + i;
#pragma unroll
        for (int j = 0; j < 8; j++) {
            const int n = bn * 128 + tcol * 8 + j;
            const float v = acc[i][j] + bias[n];
            if (mode == 0) {
                // [B,H,S,D] layout
                const int b = m >> 11;       // /2048
                const int s = m & 2047;
                const int h = n >> 6;        // /64
                const int d = n & 63;
                C[(((size_t)(b * NHEAD + h) * SEQ) + s) * HDIM + d] = v;
            } else {
                C[(size_t)m * EMB + n] = v;
            }
        }
    }
}

// ---------------------------------------------------------------------------
// Flash attention (fp32). One thread per query row, 128 rows per block.
// grid.x = SEQ/128 = 16, grid.y = B*H = 32.
// ---------------------------------------------------------------------------
__global__ void __launch_bounds__(128)
attn_kernel(const float* __restrict__ Q, const float* __restrict__ K,
            const float* __restrict__ V, float* __restrict__ O)
{
    __shared__ float ks[32 * 64];
    __shared__ float vs[32 * 64];

    const int tid = threadIdx.x;
    const int qt  = blockIdx.x;
    const int bh  = blockIdx.y;

    const float* Qb = Q + (size_t)bh * SEQ * HDIM;
    const float* Kb = K + (size_t)bh * SEQ * HDIM;
    const float* Vb = V + (size_t)bh * SEQ * HDIM;

    const int row = qt * 128 + tid;

    // Load query row into registers
    float q[64];
    {
        const float4* qp = (const float4*)(Qb + (size_t)row * HDIM);
#pragma unroll
        for (int i = 0; i < 16; i++) {
            float4 t = qp[i];
            q[4*i+0] = t.x; q[4*i+1] = t.y; q[4*i+2] = t.z; q[4*i+3] = t.w;
        }
    }

    float o[64];
#pragma unroll
    for (int e = 0; e < 64; e++) o[e] = 0.f;
    float mx = -1e30f;
    float l  = 0.f;

    for (int kt = 0; kt < SEQ; kt += 32) {
        __syncthreads();
        {
            const float4* kg = (const float4*)(Kb + (size_t)kt * HDIM);
            const float4* vg = (const float4*)(Vb + (size_t)kt * HDIM);
            float4* k4 = (float4*)ks;
            float4* v4 = (float4*)vs;
#pragma unroll
            for (int i = 0; i < 4; i++) {
                k4[tid + i * 128] = kg[tid + i * 128];
                v4[tid + i * 128] = vg[tid + i * 128];
            }
        }
        __syncthreads();

        float s[32];
        float tmax = mx;
#pragma unroll
        for (int j = 0; j < 32; j++) {
            const float4* kr = (const float4*)(ks + j * 64);
            float a0 = 0.f, a1 = 0.f, a2 = 0.f, a3 = 0.f;
#pragma unroll
            for (int e = 0; e < 16; e++) {
                float4 kv = kr[e];
                a0 = fmaf(q[4*e+0], kv.x, a0);
                a1 = fmaf(q[4*e+1], kv.y, a1);
                a2 = fmaf(q[4*e+2], kv.z, a2);
                a3 = fmaf(q[4*e+3], kv.w, a3);
            }
            s[j] = (a0 + a1 + a2 + a3) * 0.125f;   // 1/sqrt(64)
            tmax = fmaxf(tmax, s[j]);
        }

        const float rescale = __expf(mx - tmax);
        l *= rescale;
#pragma unroll
        for (int e = 0; e < 64; e++) o[e] *= rescale;
        mx = tmax;

#pragma unroll
        for (int j = 0; j < 32; j++) {
            const float p = __expf(s[j] - mx);
            l += p;
            const float4* vr = (const float4*)(vs + j * 64);
#pragma unroll
            for (int e = 0; e < 16; e++) {
                float4 vv = vr[e];
                o[4*e+0] = fmaf(p, vv.x, o[4*e+0]);
                o[4*e+1] = fmaf(p, vv.y, o[4*e+1]);
                o[4*e+2] = fmaf(p, vv.z, o[4*e+2]);
                o[4*e+3] = fmaf(p, vv.w, o[4*e+3]);
            }
        }
    }

    const float inv = 1.f / l;
    const int b = bh >> 4;
    const int h = bh & 15;
    float* op = O + ((size_t)(b * SEQ + row)) * EMB + h * HDIM;
    float4* op4 = (float4*)op;
#pragma unroll
    for (int e = 0; e < 16; e++) {
        float4 t;
        t.x = o[4*e+0] * inv; t.y = o[4*e+1] * inv;
        t.z = o[4*e+2] * inv; t.w = o[4*e+3] * inv;
        op4[e] = t;
    }
}

// ---------------------------------------------------------------------------
// Launch
// ---------------------------------------------------------------------------
extern "C" void kernel_launch(void* const* d_in, const int* in_sizes, int n_in,
                              void* d_out, int out_size)
{
    const float* X   = (const float*)d_in[0];
    const float* W_q = (const float*)d_in[1];
    const float* b_q = (const float*)d_in[2];
    const float* W_k = (const float*)d_in[3];
    const float* b_k = (const float*)d_in[4];
    const float* W_v = (const float*)d_in[5];
    const float* b_v = (const float*)d_in[6];
    const float* W_o = (const float*)d_in[7];
    const float* b_o = (const float*)d_in[8];
    float* out = (float*)d_out;

    float *Qp, *Kp, *Vp, *Ap;
    cudaGetSymbolAddress((void**)&Qp, g_Q);
    cudaGetSymbolAddress((void**)&Kp, g_K);
    cudaGetSymbolAddress((void**)&Vp, g_V);
    cudaGetSymbolAddress((void**)&Ap, g_attn);

    dim3 ggrid(8, 32);   // N/128, M/128
    dim3 gthr(256);

    gemm_bias_kernel<<<ggrid, gthr>>>(X, W_q, b_q, Qp, 0);
    gemm_bias_kernel<<<ggrid, gthr>>>(X, W_k, b_k, Kp, 0);
    gemm_bias_kernel<<<ggrid, gthr>>>(X, W_v, b_v, Vp, 0);

    dim3 agrid(SEQ / 128, BATCH * NHEAD);
    attn_kernel<<<agrid, 128>>>(Qp, Kp, Vp, Ap);

    gemm_bias_kernel<<<ggrid, gthr>>>(Ap, W_o, b_o, out, 1);
}

// round 2
// speedup vs baseline: 1.2412x; 1.2412x over previous
#include <cuda_runtime.h>
#include <cuda_bf16.h>
#include <stdint.h>
#include <math.h>

// Problem constants
#define BATCH   2
#define SEQ     2048
#define EMB     1024
#define NHEAD   16
#define HDIM    64
#define MROWS   (BATCH * SEQ)          // 4096
#define K3      (3 * EMB)              // 3072 (split-precision concat K)
#define QKV_ELEMS (BATCH * NHEAD * SEQ * HDIM)

// Scratch (__device__ globals: allocation-free rule)
__device__ float g_Q[QKV_ELEMS];
__device__ float g_K[QKV_ELEMS];
__device__ float g_V[QKV_ELEMS];
__device__ float g_attn[MROWS * EMB];
__device__ __nv_bfloat16 g_Xs[(size_t)MROWS * K3];       // X split
__device__ __nv_bfloat16 g_Ws[4][(size_t)EMB * K3];      // 4 weights split
__device__ __nv_bfloat16 g_As[(size_t)MROWS * K3];       // attn-out split

// ---------------------------------------------------------------------------
// Split-precision conversion: fp32 -> [hi, hi, lo] (mode 0, activations)
//                                  -> [hi, lo, hi] (mode 1, weights)
// in:  rows x 1024 fp32 ; out: rows x 3072 bf16
// ---------------------------------------------------------------------------
__global__ void split_kernel(const float* __restrict__ in,
                             __nv_bfloat16* __restrict__ out,
                             int rows, int mode)
{
    int idx = blockIdx.x * blockDim.x + threadIdx.x;
    if (idx >= rows * EMB) return;
    int r = idx >> 10;
    int k = idx & 1023;
    float x = in[idx];
    __nv_bfloat16 hi = __float2bfloat16(x);
    __nv_bfloat16 lo = __float2bfloat16(x - __bfloat162float(hi));
    __nv_bfloat16* o = out + (size_t)r * K3 + k;
    o[0]    = hi;
    o[1024] = mode ? lo : hi;
    o[2048] = mode ? hi : lo;
}

// ---------------------------------------------------------------------------
// bf16 HMMA GEMM with fp32 accumulate.
// C[m,n] = sum_k A'[m,k] * B'[n,k] + bias[n]     (K = 3072)
// Block tile 128x128, 8 warps each 64x32, double-buffered smem.
// mode 0: C written in [B,H,S,D] layout ; mode 1: row-major [M, EMB]
// ---------------------------------------------------------------------------
#define SPAD 40   // padded smem row stride (bf16 elems) -> conflict-free frags

__device__ __forceinline__ void mma16816(float* c, const uint32_t* a, const uint32_t* b)
{
    asm volatile(
        "mma.sync.aligned.m16n8k16.row.col.f32.bf16.bf16.f32 "
        "{%0,%1,%2,%3}, {%4,%5,%6,%7}, {%8,%9}, {%0,%1,%2,%3};"
        : "+f"(c[0]), "+f"(c[1]), "+f"(c[2]), "+f"(c[3])
        : "r"(a[0]), "r"(a[1]), "r"(a[2]), "r"(a[3]), "r"(b[0]), "r"(b[1]));
}

__global__ void __launch_bounds__(256, 2)
gemm_mma_kernel(const __nv_bfloat16* __restrict__ A,
                const __nv_bfloat16* __restrict__ B,
                const float* __restrict__ bias,
                float* __restrict__ C, int mode)
{
    __shared__ __nv_bfloat16 As[2][128][SPAD];
    __shared__ __nv_bfloat16 Bs[2][128][SPAD];

    const int tid  = threadIdx.x;
    const int bm   = blockIdx.y;
    const int bn   = blockIdx.x;
    const int wid  = tid >> 5;
    const int lane = tid & 31;
    const int g    = lane >> 2;     // 0..7
    const int t    = lane & 3;      // 0..3
    const int wm   = (wid >> 2) * 64;   // warp m offset in tile
    const int wn   = (wid & 3) * 32;    // warp n offset in tile

    // global staging: thread loads one row, 16 consecutive k (two uint4)
    const int lrow = tid >> 1;
    const int lk   = (tid & 1) * 16;
    const __nv_bfloat16* Ag = A + (size_t)(bm * 128 + lrow) * K3 + lk;
    const __nv_bfloat16* Bg = B + (size_t)(bn * 128 + lrow) * K3 + lk;

    float acc[4][4][4];
#pragma unroll
    for (int i = 0; i < 4; i++)
#pragma unroll
        for (int j = 0; j < 4; j++)
#pragma unroll
            for (int q = 0; q < 4; q++) acc[i][j][q] = 0.f;

    // prologue: stage 0
    uint4 ra0 = *(const uint4*)(Ag);
    uint4 ra1 = *(const uint4*)(Ag + 8);
    uint4 rb0 = *(const uint4*)(Bg);
    uint4 rb1 = *(const uint4*)(Bg + 8);
    *(uint4*)&As[0][lrow][lk]     = ra0;
    *(uint4*)&As[0][lrow][lk + 8] = ra1;
    *(uint4*)&Bs[0][lrow][lk]     = rb0;
    *(uint4*)&Bs[0][lrow][lk + 8] = rb1;
    __syncthreads();

    int s = 0;
    for (int k0 = 0; k0 < K3; k0 += 32) {
        const bool more = (k0 + 32) < K3;
        if (more) {
            ra0 = *(const uint4*)(Ag + k0 + 32);
            ra1 = *(const uint4*)(Ag + k0 + 40);
            rb0 = *(const uint4*)(Bg + k0 + 32);
            rb1 = *(const uint4*)(Bg + k0 + 40);
        }

        // compute on stage s (two k16 steps)
#pragma unroll
        for (int kk = 0; kk < 32; kk += 16) {
            uint32_t af[4][4], bf[4][2];
#pragma unroll
            for (int mi = 0; mi < 4; mi++) {
                const __nv_bfloat16* p = &As[s][wm + mi * 16 + g][kk + 2 * t];
                af[mi][0] = *(const uint32_t*)(p);
                af[mi][1] = *(const uint32_t*)(p + 8 * SPAD);
                af[mi][2] = *(const uint32_t*)(p + 8);
                af[mi][3] = *(const uint32_t*)(p + 8 * SPAD + 8);
            }
#pragma unroll
            for (int ni = 0; ni < 4; ni++) {
                const __nv_bfloat16* p = &Bs[s][wn + ni * 8 + g][kk + 2 * t];
                bf[ni][0] = *(const uint32_t*)(p);
                bf[ni][1] = *(const uint32_t*)(p + 8);
            }
#pragma unroll
            for (int mi = 0; mi < 4; mi++)
#pragma unroll
                for (int ni = 0; ni < 4; ni++)
                    mma16816(acc[mi][ni], af[mi], bf[ni]);
        }

        if (more) {
            *(uint4*)&As[s ^ 1][lrow][lk]     = ra0;
            *(uint4*)&As[s ^ 1][lrow][lk + 8] = ra1;
            *(uint4*)&Bs[s ^ 1][lrow][lk]     = rb0;
            *(uint4*)&Bs[s ^ 1][lrow][lk + 8] = rb1;
            __syncthreads();
            s ^= 1;
        }
    }

    // epilogue
#pragma unroll
    for (int mi = 0; mi < 4; mi++) {
        const int r0 = bm * 128 + wm + mi * 16 + g;
#pragma unroll
        for (int ni = 0; ni < 4; ni++) {
            const int c = bn * 128 + wn + ni * 8 + 2 * t;
            const float bv0 = bias[c], bv1 = bias[c + 1];
            float2 v0 = make_float2(acc[mi][ni][0] + bv0, acc[mi][ni][1] + bv1);
            float2 v1 = make_float2(acc[mi][ni][2] + bv0, acc[mi][ni][3] + bv1);
            if (mode == 0) {
                const int b = r0 >> 11, sq = r0 & 2047;
                const int h = c >> 6,  d  = c & 63;
                float* p0 = &((float*)0)[0]; (void)p0;
                float* base = (float*)C;
                size_t off0 = (((size_t)(b * NHEAD + h) * SEQ) + sq) * HDIM + d;
                size_t off1 = (((size_t)(b * NHEAD + h) * SEQ) + (sq + 8)) * HDIM + d;
                // r0 and r0+8 are in the same (b,h); sq+8 < SEQ since g<8, mi*16+wm+... tile-aligned
                *(float2*)(base + off0) = v0;
                *(float2*)(base + off1) = v1;
            } else {
                *(float2*)(C + (size_t)r0 * EMB + c)       = v0;
                *(float2*)(C + (size_t)(r0 + 8) * EMB + c) = v1;
            }
        }
    }
}

// ---------------------------------------------------------------------------
// Flash attention (fp32), unchanged from Round 0.
// ---------------------------------------------------------------------------
__global__ void __launch_bounds__(128)
attn_kernel(const float* __restrict__ Q, const float* __restrict__ K,
            const float* __restrict__ V, float* __restrict__ O)
{
    __shared__ float ks[32 * 64];
    __shared__ float vs[32 * 64];

    const int tid = threadIdx.x;
    const int qt  = blockIdx.x;
    const int bh  = blockIdx.y;

    const float* Qb = Q + (size_t)bh * SEQ * HDIM;
    const float* Kb = K + (size_t)bh * SEQ * HDIM;
    const float* Vb = V + (size_t)bh * SEQ * HDIM;

    const int row = qt * 128 + tid;

    float q[64];
    {
        const float4* qp = (const float4*)(Qb + (size_t)row * HDIM);
#pragma unroll
        for (int i = 0; i < 16; i++) {
            float4 tv = qp[i];
            q[4*i+0] = tv.x; q[4*i+1] = tv.y; q[4*i+2] = tv.z; q[4*i+3] = tv.w;
        }
    }

    float o[64];
#pragma unroll
    for (int e = 0; e < 64; e++) o[e] = 0.f;
    float mx = -1e30f;
    float l  = 0.f;

    for (int kt = 0; kt < SEQ; kt += 32) {
        __syncthreads();
        {
            const float4* kg = (const float4*)(Kb + (size_t)kt * HDIM);
            const float4* vg = (const float4*)(Vb + (size_t)kt * HDIM);
            float4* k4 = (float4*)ks;
            float4* v4 = (float4*)vs;
#pragma unroll
            for (int i = 0; i < 4; i++) {
                k4[tid + i * 128] = kg[tid + i * 128];
                v4[tid + i * 128] = vg[tid + i * 128];
            }
        }
        __syncthreads();

        float sx[32];
        float tmax = mx;
#pragma unroll
        for (int j = 0; j < 32; j++) {
            const float4* kr = (const float4*)(ks + j * 64);
            float a0 = 0.f, a1 = 0.f, a2 = 0.f, a3 = 0.f;
#pragma unroll
            for (int e = 0; e < 16; e++) {
                float4 kv = kr[e];
                a0 = fmaf(q[4*e+0], kv.x, a0);
                a1 = fmaf(q[4*e+1], kv.y, a1);
                a2 = fmaf(q[4*e+2], kv.z, a2);
                a3 = fmaf(q[4*e+3], kv.w, a3);
            }
            sx[j] = (a0 + a1 + a2 + a3) * 0.125f;
            tmax = fmaxf(tmax, sx[j]);
        }

        const float rescale = __expf(mx - tmax);
        l *= rescale;
#pragma unroll
        for (int e = 0; e < 64; e++) o[e] *= rescale;
        mx = tmax;

#pragma unroll
        for (int j = 0; j < 32; j++) {
            const float p = __expf(sx[j] - mx);
            l += p;
            const float4* vr = (const float4*)(vs + j * 64);
#pragma unroll
            for (int e = 0; e < 16; e++) {
                float4 vv = vr[e];
                o[4*e+0] = fmaf(p, vv.x, o[4*e+0]);
                o[4*e+1] = fmaf(p, vv.y, o[4*e+1]);
                o[4*e+2] = fmaf(p, vv.z, o[4*e+2]);
                o[4*e+3] = fmaf(p, vv.w, o[4*e+3]);
            }
        }
    }

    const float inv = 1.f / l;
    const int b = bh >> 4;
    const int h = bh & 15;
    float* op = O + ((size_t)(b * SEQ + row)) * EMB + h * HDIM;
    float4* op4 = (float4*)op;
#pragma unroll
    for (int e = 0; e < 16; e++) {
        float4 tv;
        tv.x = o[4*e+0] * inv; tv.y = o[4*e+1] * inv;
        tv.z = o[4*e+2] * inv; tv.w = o[4*e+3] * inv;
        op4[e] = tv;
    }
}

// ---------------------------------------------------------------------------
// Launch
// ---------------------------------------------------------------------------
extern "C" void kernel_launch(void* const* d_in, const int* in_sizes, int n_in,
                              void* d_out, int out_size)
{
    const float* X   = (const float*)d_in[0];
    const float* W_q = (const float*)d_in[1];
    const float* b_q = (const float*)d_in[2];
    const float* W_k = (const float*)d_in[3];
    const float* b_k = (const float*)d_in[4];
    const float* W_v = (const float*)d_in[5];
    const float* b_v = (const float*)d_in[6];
    const float* W_o = (const float*)d_in[7];
    const float* b_o = (const float*)d_in[8];
    float* out = (float*)d_out;

    float *Qp, *Kp, *Vp, *Ap;
    __nv_bfloat16 *Xs, *Ws, *As;
    cudaGetSymbolAddress((void**)&Qp, g_Q);
    cudaGetSymbolAddress((void**)&Kp, g_K);
    cudaGetSymbolAddress((void**)&Vp, g_V);
    cudaGetSymbolAddress((void**)&Ap, g_attn);
    cudaGetSymbolAddress((void**)&Xs, g_Xs);
    cudaGetSymbolAddress((void**)&Ws, g_Ws);
    cudaGetSymbolAddress((void**)&As, g_As);

    const int cthr = 256;
    // conversions
    split_kernel<<<(MROWS * EMB + cthr - 1) / cthr, cthr>>>(X, Xs, MROWS, 0);
    split_kernel<<<(EMB * EMB + cthr - 1) / cthr, cthr>>>(W_q, Ws + 0 * (size_t)EMB * K3, EMB, 1);
    split_kernel<<<(EMB * EMB + cthr - 1) / cthr, cthr>>>(W_k, Ws + 1 * (size_t)EMB * K3, EMB, 1);
    split_kernel<<<(EMB * EMB + cthr - 1) / cthr, cthr>>>(W_v, Ws + 2 * (size_t)EMB * K3, EMB, 1);
    split_kernel<<<(EMB * EMB + cthr - 1) / cthr, cthr>>>(W_o, Ws + 3 * (size_t)EMB * K3, EMB, 1);

    dim3 ggrid(EMB / 128, MROWS / 128);   // (8, 32)
    gemm_mma_kernel<<<ggrid, 256>>>(Xs, Ws + 0 * (size_t)EMB * K3, b_q, Qp, 0);
    gemm_mma_kernel<<<ggrid, 256>>>(Xs, Ws + 1 * (size_t)EMB * K3, b_k, Kp, 0);
    gemm_mma_kernel<<<ggrid, 256>>>(Xs, Ws + 2 * (size_t)EMB * K3, b_v, Vp, 0);

    dim3 agrid(SEQ / 128, BATCH * NHEAD);
    attn_kernel<<<agrid, 128>>>(Qp, Kp, Vp, Ap);

    split_kernel<<<(MROWS * EMB + cthr - 1) / cthr, cthr>>>(Ap, As, MROWS, 0);
    gemm_mma_kernel<<<ggrid, 256>>>(As, Ws + 3 * (size_t)EMB * K3, b_o, out, 1);
}

// round 3
// speedup vs baseline: 2.1317x; 1.7174x over previous
#include <cuda_runtime.h>
#include <cuda_bf16.h>
#include <stdint.h>
#include <math.h>

#define BATCH   2
#define SEQ     2048
#define EMB     1024
#define NHEAD   16
#define HDIM    64
#define MROWS   (BATCH * SEQ)
#define K3      (3 * EMB)
#define QKV_ELEMS (BATCH * NHEAD * SEQ * HDIM)

// Scratch (__device__ globals)
__device__ __nv_bfloat16 g_Qhi[QKV_ELEMS];
__device__ __nv_bfloat16 g_Qlo[QKV_ELEMS];
__device__ __nv_bfloat16 g_Khi[QKV_ELEMS];
__device__ __nv_bfloat16 g_Klo[QKV_ELEMS];
__device__ __nv_bfloat16 g_Vhi[QKV_ELEMS];
__device__ __nv_bfloat16 g_Vlo[QKV_ELEMS];
__device__ __nv_bfloat16 g_Xs[(size_t)MROWS * K3];
__device__ __nv_bfloat16 g_Ws[4][(size_t)EMB * K3];
__device__ __nv_bfloat16 g_As[(size_t)MROWS * K3];

// ---------------------------------------------------------------------------
__device__ __forceinline__ void hilo2(float x, float y, uint32_t& hi, uint32_t& lo)
{
    __nv_bfloat16 hx = __float2bfloat16(x), hy = __float2bfloat16(y);
    __nv_bfloat16 lx = __float2bfloat16(x - __bfloat162float(hx));
    __nv_bfloat16 ly = __float2bfloat16(y - __bfloat162float(hy));
    __nv_bfloat162 h2; h2.x = hx; h2.y = hy;
    __nv_bfloat162 l2; l2.x = lx; l2.y = ly;
    hi = *(uint32_t*)&h2;
    lo = *(uint32_t*)&l2;
}

__device__ __forceinline__ void mma16816(float* c, const uint32_t* a, const uint32_t* b)
{
    asm volatile(
        "mma.sync.aligned.m16n8k16.row.col.f32.bf16.bf16.f32 "
        "{%0,%1,%2,%3}, {%4,%5,%6,%7}, {%8,%9}, {%0,%1,%2,%3};"
        : "+f"(c[0]), "+f"(c[1]), "+f"(c[2]), "+f"(c[3])
        : "r"(a[0]), "r"(a[1]), "r"(a[2]), "r"(a[3]), "r"(b[0]), "r"(b[1]));
}

// ---------------------------------------------------------------------------
// Split conversion: fp32 -> [hi, hi, lo] (mode 0 activations) / [hi, lo, hi] (mode 1 weights)
// ---------------------------------------------------------------------------
__global__ void split_kernel(const float* __restrict__ in,
                             __nv_bfloat16* __restrict__ out,
                             int rows, int mode)
{
    int idx = blockIdx.x * blockDim.x + threadIdx.x;
    if (idx >= rows * EMB) return;
    int r = idx >> 10;
    int k = idx & 1023;
    float x = in[idx];
    __nv_bfloat16 hi = __float2bfloat16(x);
    __nv_bfloat16 lo = __float2bfloat16(x - __bfloat162float(hi));
    __nv_bfloat16* o = out + (size_t)r * K3 + k;
    o[0]    = hi;
    o[1024] = mode ? lo : hi;
    o[2048] = mode ? hi : lo;
}

// ---------------------------------------------------------------------------
// bf16 HMMA GEMM, K=3072, 128x128 tile, 8 warps.
// mode 0: write split hi/lo bf16 in [B,H,S,D]; mode 1: fp32 row-major [M,EMB]
// ---------------------------------------------------------------------------
#define SPAD 40

__global__ void __launch_bounds__(256, 2)
gemm_mma_kernel(const __nv_bfloat16* __restrict__ A,
                const __nv_bfloat16* __restrict__ B,
                const float* __restrict__ bias,
                __nv_bfloat16* __restrict__ Chi,
                __nv_bfloat16* __restrict__ Clo,
                float* __restrict__ Cf, int mode)
{
    __shared__ __nv_bfloat16 As[2][128][SPAD];
    __shared__ __nv_bfloat16 Bs[2][128][SPAD];

    const int tid  = threadIdx.x;
    const int bm   = blockIdx.y;
    const int bn   = blockIdx.x;
    const int wid  = tid >> 5;
    const int lane = tid & 31;
    const int g    = lane >> 2;
    const int t    = lane & 3;
    const int wm   = (wid >> 2) * 64;
    const int wn   = (wid & 3) * 32;

    const int lrow = tid >> 1;
    const int lk   = (tid & 1) * 16;
    const __nv_bfloat16* Ag = A + (size_t)(bm * 128 + lrow) * K3 + lk;
    const __nv_bfloat16* Bg = B + (size_t)(bn * 128 + lrow) * K3 + lk;

    float acc[4][4][4];
#pragma unroll
    for (int i = 0; i < 4; i++)
#pragma unroll
        for (int j = 0; j < 4; j++)
#pragma unroll
            for (int q = 0; q < 4; q++) acc[i][j][q] = 0.f;

    uint4 ra0 = *(const uint4*)(Ag);
    uint4 ra1 = *(const uint4*)(Ag + 8);
    uint4 rb0 = *(const uint4*)(Bg);
    uint4 rb1 = *(const uint4*)(Bg + 8);
    *(uint4*)&As[0][lrow][lk]     = ra0;
    *(uint4*)&As[0][lrow][lk + 8] = ra1;
    *(uint4*)&Bs[0][lrow][lk]     = rb0;
    *(uint4*)&Bs[0][lrow][lk + 8] = rb1;
    __syncthreads();

    int s = 0;
    for (int k0 = 0; k0 < K3; k0 += 32) {
        const bool more = (k0 + 32) < K3;
        if (more) {
            ra0 = *(const uint4*)(Ag + k0 + 32);
            ra1 = *(const uint4*)(Ag + k0 + 40);
            rb0 = *(const uint4*)(Bg + k0 + 32);
            rb1 = *(const uint4*)(Bg + k0 + 40);
        }

#pragma unroll
        for (int kk = 0; kk < 32; kk += 16) {
            uint32_t af[4][4], bf[4][2];
#pragma unroll
            for (int mi = 0; mi < 4; mi++) {
                const __nv_bfloat16* p = &As[s][wm + mi * 16 + g][kk + 2 * t];
                af[mi][0] = *(const uint32_t*)(p);
                af[mi][1] = *(const uint32_t*)(p + 8 * SPAD);
                af[mi][2] = *(const uint32_t*)(p + 8);
                af[mi][3] = *(const uint32_t*)(p + 8 * SPAD + 8);
            }
#pragma unroll
            for (int ni = 0; ni < 4; ni++) {
                const __nv_bfloat16* p = &Bs[s][wn + ni * 8 + g][kk + 2 * t];
                bf[ni][0] = *(const uint32_t*)(p);
                bf[ni][1] = *(const uint32_t*)(p + 8);
            }
#pragma unroll
            for (int mi = 0; mi < 4; mi++)
#pragma unroll
                for (int ni = 0; ni < 4; ni++)
                    mma16816(acc[mi][ni], af[mi], bf[ni]);
        }

        if (more) {
            *(uint4*)&As[s ^ 1][lrow][lk]     = ra0;
            *(uint4*)&As[s ^ 1][lrow][lk + 8] = ra1;
            *(uint4*)&Bs[s ^ 1][lrow][lk]     = rb0;
            *(uint4*)&Bs[s ^ 1][lrow][lk + 8] = rb1;
            __syncthreads();
            s ^= 1;
        }
    }

#pragma unroll
    for (int mi = 0; mi < 4; mi++) {
        const int r0 = bm * 128 + wm + mi * 16 + g;
#pragma unroll
        for (int ni = 0; ni < 4; ni++) {
            const int c = bn * 128 + wn + ni * 8 + 2 * t;
            const float bv0 = bias[c], bv1 = bias[c + 1];
            float v00 = acc[mi][ni][0] + bv0, v01 = acc[mi][ni][1] + bv1;
            float v10 = acc[mi][ni][2] + bv0, v11 = acc[mi][ni][3] + bv1;
            if (mode == 0) {
                const int b = r0 >> 11, sq = r0 & 2047;
                const int h = c >> 6,  d  = c & 63;
                size_t off0 = (((size_t)(b * NHEAD + h) * SEQ) + sq) * HDIM + d;
                size_t off1 = off0 + 8 * HDIM;
                uint32_t hi0, lo0, hi1, lo1;
                hilo2(v00, v01, hi0, lo0);
                hilo2(v10, v11, hi1, lo1);
                *(uint32_t*)(Chi + off0) = hi0;
                *(uint32_t*)(Clo + off0) = lo0;
                *(uint32_t*)(Chi + off1) = hi1;
                *(uint32_t*)(Clo + off1) = lo1;
            } else {
                *(float2*)(Cf + (size_t)r0 * EMB + c)       = make_float2(v00, v01);
                *(float2*)(Cf + (size_t)(r0 + 8) * EMB + c) = make_float2(v10, v11);
            }
        }
    }
}

// ---------------------------------------------------------------------------
// Tensor-core flash attention, split-bf16.
// Block: 128 threads (4 warps), Br=64 q rows, Bc=64 keys/iter.
// grid = (SEQ/64 = 32, B*H = 32). Output written as split activations to g_As.
// ---------------------------------------------------------------------------
#define ASTR 72

__global__ void __launch_bounds__(128)
attn_mma_kernel(const __nv_bfloat16* __restrict__ Qhi, const __nv_bfloat16* __restrict__ Qlo,
                const __nv_bfloat16* __restrict__ Khi, const __nv_bfloat16* __restrict__ Klo,
                const __nv_bfloat16* __restrict__ Vhi, const __nv_bfloat16* __restrict__ Vlo,
                __nv_bfloat16* __restrict__ Out)
{
    __shared__ __nv_bfloat16 sKhi[64][ASTR];
    __shared__ __nv_bfloat16 sKlo[64][ASTR];
    __shared__ __nv_bfloat16 sVhi[64][ASTR];   // transposed: [d][token]
    __shared__ __nv_bfloat16 sVlo[64][ASTR];

    const int tid  = threadIdx.x;
    const int wid  = tid >> 5;
    const int lane = tid & 31;
    const int g    = lane >> 2;
    const int t    = lane & 3;
    const int qt   = blockIdx.x;
    const int bh   = blockIdx.y;
    const size_t base = (size_t)bh * SEQ * HDIM;

    // --- Stage Q tile (hi->sKhi, lo->sKlo), extract A fragments ---
#pragma unroll
    for (int i = 0; i < 4; i++) {
        int idx = tid + 128 * i;
        int row = idx >> 3;
        int co  = (idx & 7) * 8;
        *(uint4*)&sKhi[row][co] = *(const uint4*)&Qhi[base + (size_t)(qt * 64 + row) * HDIM + co];
        *(uint4*)&sKlo[row][co] = *(const uint4*)&Qlo[base + (size_t)(qt * 64 + row) * HDIM + co];
    }
    __syncthreads();

    uint32_t qh[4][4], ql[4][4];
    {
        const int r = wid * 16 + g;
#pragma unroll
        for (int kj = 0; kj < 4; kj++) {
            qh[kj][0] = *(const uint32_t*)&sKhi[r][16 * kj + 2 * t];
            qh[kj][1] = *(const uint32_t*)&sKhi[r + 8][16 * kj + 2 * t];
            qh[kj][2] = *(const uint32_t*)&sKhi[r][16 * kj + 2 * t + 8];
            qh[kj][3] = *(const uint32_t*)&sKhi[r + 8][16 * kj + 2 * t + 8];
            ql[kj][0] = *(const uint32_t*)&sKlo[r][16 * kj + 2 * t];
            ql[kj][1] = *(const uint32_t*)&sKlo[r + 8][16 * kj + 2 * t];
            ql[kj][2] = *(const uint32_t*)&sKlo[r][16 * kj + 2 * t + 8];
            ql[kj][3] = *(const uint32_t*)&sKlo[r + 8][16 * kj + 2 * t + 8];
        }
    }

    float o[8][4];
#pragma unroll
    for (int ni = 0; ni < 8; ni++)
#pragma unroll
        for (int j = 0; j < 4; j++) o[ni][j] = 0.f;
    float m0 = -1e30f, m1 = -1e30f, l0 = 0.f, l1 = 0.f;

    for (int kt = 0; kt < SEQ; kt += 64) {
        __syncthreads();
        // stage K (row-major) and V (transposed, pack 2 tokens per 32-bit word)
#pragma unroll
        for (int i = 0; i < 4; i++) {
            int idx = tid + 128 * i;
            int row = idx >> 3;
            int co  = (idx & 7) * 8;
            *(uint4*)&sKhi[row][co] = *(const uint4*)&Khi[base + (size_t)(kt + row) * HDIM + co];
            *(uint4*)&sKlo[row][co] = *(const uint4*)&Klo[base + (size_t)(kt + row) * HDIM + co];
        }
#pragma unroll
        for (int it = 0; it < 2; it++) {
            int idx = tid + 128 * it;
            int rp  = idx & 31;          // token pair
            int cg  = (idx >> 5) * 8;    // d group
            uint4 h0 = *(const uint4*)&Vhi[base + (size_t)(kt + 2 * rp) * HDIM + cg];
            uint4 h1 = *(const uint4*)&Vhi[base + (size_t)(kt + 2 * rp + 1) * HDIM + cg];
            uint4 w0 = *(const uint4*)&Vlo[base + (size_t)(kt + 2 * rp) * HDIM + cg];
            uint4 w1 = *(const uint4*)&Vlo[base + (size_t)(kt + 2 * rp + 1) * HDIM + cg];
            const __nv_bfloat16* a0 = (const __nv_bfloat16*)&h0;
            const __nv_bfloat16* a1 = (const __nv_bfloat16*)&h1;
            const __nv_bfloat16* c0 = (const __nv_bfloat16*)&w0;
            const __nv_bfloat16* c1 = (const __nv_bfloat16*)&w1;
#pragma unroll
            for (int e = 0; e < 8; e++) {
                __nv_bfloat162 ph; ph.x = a0[e]; ph.y = a1[e];
                __nv_bfloat162 pl; pl.x = c0[e]; pl.y = c1[e];
                *(uint32_t*)&sVhi[cg + e][2 * rp] = *(uint32_t*)&ph;
                *(uint32_t*)&sVlo[cg + e][2 * rp] = *(uint32_t*)&pl;
            }
        }
        __syncthreads();

        // --- S = Q K^T (split, 3 terms) ---
        float sc[8][4];
#pragma unroll
        for (int ni = 0; ni < 8; ni++)
#pragma unroll
            for (int j = 0; j < 4; j++) sc[ni][j] = 0.f;

#pragma unroll
        for (int kj = 0; kj < 4; kj++) {
#pragma unroll
            for (int ni = 0; ni < 8; ni++) {
                uint32_t bh_[2], bl_[2];
                bh_[0] = *(const uint32_t*)&sKhi[8 * ni + g][16 * kj + 2 * t];
                bh_[1] = *(const uint32_t*)&sKhi[8 * ni + g][16 * kj + 2 * t + 8];
                bl_[0] = *(const uint32_t*)&sKlo[8 * ni + g][16 * kj + 2 * t];
                bl_[1] = *(const uint32_t*)&sKlo[8 * ni + g][16 * kj + 2 * t + 8];
                mma16816(sc[ni], qh[kj], bh_);
                mma16816(sc[ni], qh[kj], bl_);
                mma16816(sc[ni], ql[kj], bh_);
            }
        }

        // --- online softmax ---
        float mx0 = -1e30f, mx1 = -1e30f;
#pragma unroll
        for (int ni = 0; ni < 8; ni++) {
            sc[ni][0] *= 0.125f; sc[ni][1] *= 0.125f;
            sc[ni][2] *= 0.125f; sc[ni][3] *= 0.125f;
            mx0 = fmaxf(mx0, fmaxf(sc[ni][0], sc[ni][1]));
            mx1 = fmaxf(mx1, fmaxf(sc[ni][2], sc[ni][3]));
        }
        mx0 = fmaxf(mx0, __shfl_xor_sync(0xffffffff, mx0, 1));
        mx0 = fmaxf(mx0, __shfl_xor_sync(0xffffffff, mx0, 2));
        mx1 = fmaxf(mx1, __shfl_xor_sync(0xffffffff, mx1, 1));
        mx1 = fmaxf(mx1, __shfl_xor_sync(0xffffffff, mx1, 2));

        const float nm0 = fmaxf(m0, mx0);
        const float nm1 = fmaxf(m1, mx1);
        const float rs0 = __expf(m0 - nm0);
        const float rs1 = __expf(m1 - nm1);
        m0 = nm0; m1 = nm1;
        l0 *= rs0; l1 *= rs1;
#pragma unroll
        for (int ni = 0; ni < 8; ni++) {
            o[ni][0] *= rs0; o[ni][1] *= rs0;
            o[ni][2] *= rs1; o[ni][3] *= rs1;
            sc[ni][0] = __expf(sc[ni][0] - m0);
            sc[ni][1] = __expf(sc[ni][1] - m0);
            sc[ni][2] = __expf(sc[ni][2] - m1);
            sc[ni][3] = __expf(sc[ni][3] - m1);
            l0 += sc[ni][0] + sc[ni][1];
            l1 += sc[ni][2] + sc[ni][3];
        }

        // --- O += P V (split, 3 terms) ---
#pragma unroll
        for (int kj = 0; kj < 4; kj++) {
            uint32_t ah[4], al[4];
            hilo2(sc[2 * kj][0],     sc[2 * kj][1],     ah[0], al[0]);
            hilo2(sc[2 * kj][2],     sc[2 * kj][3],     ah[1], al[1]);
            hilo2(sc[2 * kj + 1][0], sc[2 * kj + 1][1], ah[2], al[2]);
            hilo2(sc[2 * kj + 1][2], sc[2 * kj + 1][3], ah[3], al[3]);
#pragma unroll
            for (int ni = 0; ni < 8; ni++) {
                uint32_t bh_[2], bl_[2];
                bh_[0] = *(const uint32_t*)&sVhi[8 * ni + g][16 * kj + 2 * t];
                bh_[1] = *(const uint32_t*)&sVhi[8 * ni + g][16 * kj + 2 * t + 8];
                bl_[0] = *(const uint32_t*)&sVlo[8 * ni + g][16 * kj + 2 * t];
                bl_[1] = *(const uint32_t*)&sVlo[8 * ni + g][16 * kj + 2 * t + 8];
                mma16816(o[ni], ah, bh_);
                mma16816(o[ni], ah, bl_);
                mma16816(o[ni], al, bh_);
            }
        }
    }

    // --- finalize: normalize and write split activations [hi,hi,lo] ---
    l0 += __shfl_xor_sync(0xffffffff, l0, 1);
    l0 += __shfl_xor_sync(0xffffffff, l0, 2);
    l1 += __shfl_xor_sync(0xffffffff, l1, 1);
    l1 += __shfl_xor_sync(0xffffffff, l1, 2);
    const float inv0 = 1.f / l0;
    const float inv1 = 1.f / l1;

    const int s0 = qt * 64 + wid * 16 + g;
    const int b  = bh >> 4;
    const int h  = bh & 15;
    const size_t row0 = (size_t)(b * SEQ + s0) * K3;
    const size_t row1 = row0 + (size_t)8 * K3;

#pragma unroll
    for (int ni = 0; ni < 8; ni++) {
        const int col = h * 64 + 8 * ni + 2 * t;
        uint32_t hi0, lo0, hi1, lo1;
        hilo2(o[ni][0] * inv0, o[ni][1] * inv0, hi0, lo0);
        hilo2(o[ni][2] * inv1, o[ni][3] * inv1, hi1, lo1);
        *(uint32_t*)&Out[row0 + col]        = hi0;
        *(uint32_t*)&Out[row0 + col + 1024] = hi0;
        *(uint32_t*)&Out[row0 + col + 2048] = lo0;
        *(uint32_t*)&Out[row1 + col]        = hi1;
        *(uint32_t*)&Out[row1 + col + 1024] = hi1;
        *(uint32_t*)&Out[row1 + col + 2048] = lo1;
    }
}

// ---------------------------------------------------------------------------
extern "C" void kernel_launch(void* const* d_in, const int* in_sizes, int n_in,
                              void* d_out, int out_size)
{
    const float* X   = (const float*)d_in[0];
    const float* W_q = (const float*)d_in[1];
    const float* b_q = (const float*)d_in[2];
    const float* W_k = (const float*)d_in[3];
    const float* b_k = (const float*)d_in[4];
    const float* W_v = (const float*)d_in[5];
    const float* b_v = (const float*)d_in[6];
    const float* W_o = (const float*)d_in[7];
    const float* b_o = (const float*)d_in[8];
    float* out = (float*)d_out;

    __nv_bfloat16 *Qhi, *Qlo, *Khi, *Klo, *Vhi, *Vlo, *Xs, *Ws, *As;
    cudaGetSymbolAddress((void**)&Qhi, g_Qhi);
    cudaGetSymbolAddress((void**)&Qlo, g_Qlo);
    cudaGetSymbolAddress((void**)&Khi, g_Khi);
    cudaGetSymbolAddress((void**)&Klo, g_Klo);
    cudaGetSymbolAddress((void**)&Vhi, g_Vhi);
    cudaGetSymbolAddress((void**)&Vlo, g_Vlo);
    cudaGetSymbolAddress((void**)&Xs, g_Xs);
    cudaGetSymbolAddress((void**)&Ws, g_Ws);
    cudaGetSymbolAddress((void**)&As, g_As);

    const int cthr = 256;
    split_kernel<<<(MROWS * EMB + cthr - 1) / cthr, cthr>>>(X, Xs, MROWS, 0);
    split_kernel<<<(EMB * EMB + cthr - 1) / cthr, cthr>>>(W_q, Ws + 0 * (size_t)EMB * K3, EMB, 1);
    split_kernel<<<(EMB * EMB + cthr - 1) / cthr, cthr>>>(W_k, Ws + 1 * (size_t)EMB * K3, EMB, 1);
    split_kernel<<<(EMB * EMB + cthr - 1) / cthr, cthr>>>(W_v, Ws + 2 * (size_t)EMB * K3, EMB, 1);
    split_kernel<<<(EMB * EMB + cthr - 1) / cthr, cthr>>>(W_o, Ws + 3 * (size_t)EMB * K3, EMB, 1);

    dim3 ggrid(EMB / 128, MROWS / 128);
    gemm_mma_kernel<<<ggrid, 256>>>(Xs, Ws + 0 * (size_t)EMB * K3, b_q, Qhi, Qlo, nullptr, 0);
    gemm_mma_kernel<<<ggrid, 256>>>(Xs, Ws + 1 * (size_t)EMB * K3, b_k, Khi, Klo, nullptr, 0);
    gemm_mma_kernel<<<ggrid, 256>>>(Xs, Ws + 2 * (size_t)EMB * K3, b_v, Vhi, Vlo, nullptr, 0);

    dim3 agrid(SEQ / 64, BATCH * NHEAD);
    attn_mma_kernel<<<agrid, 128>>>(Qhi, Qlo, Khi, Klo, Vhi, Vlo, As);

    gemm_mma_kernel<<<ggrid, 256>>>(As, Ws + 3 * (size_t)EMB * K3, b_o, nullptr, nullptr, out, 1);
}

// round 5
// speedup vs baseline: 2.3077x; 1.0826x over previous
#include <cuda_runtime.h>
#include <cuda_bf16.h>
#include <stdint.h>
#include <math.h>

#define BATCH   2
#define SEQ     2048
#define EMB     1024
#define NHEAD   16
#define HDIM    64
#define MROWS   (BATCH * SEQ)
#define K3      (3 * EMB)
#define QKV_ELEMS (BATCH * NHEAD * SEQ * HDIM)

// Scratch (__device__ globals)
__device__ __nv_bfloat16 g_Qhi[QKV_ELEMS];
__device__ __nv_bfloat16 g_Qlo[QKV_ELEMS];
__device__ __nv_bfloat16 g_Khi[QKV_ELEMS];
__device__ __nv_bfloat16 g_Klo[QKV_ELEMS];
__device__ __nv_bfloat16 g_Vhi[QKV_ELEMS];
__device__ __nv_bfloat16 g_Vlo[QKV_ELEMS];
__device__ __nv_bfloat16 g_Xs[(size_t)MROWS * K3];
__device__ __nv_bfloat16 g_Ws[4][(size_t)EMB * K3];   // q,k,v,o contiguous
__device__ __nv_bfloat16 g_As[(size_t)MROWS * K3];

// ---------------------------------------------------------------------------
__device__ __forceinline__ uint32_t smem_u32(const void* p) {
    uint32_t a;
    asm("{ .reg .u64 t; cvta.to.shared.u64 t, %1; cvt.u32.u64 %0, t; }" : "=r"(a) : "l"(p));
    return a;
}
#define CP_ASYNC16(dst, src) asm volatile("cp.async.cg.shared.global [%0], [%1], 16;" :: "r"(dst), "l"(src))
#define CP_COMMIT()  asm volatile("cp.async.commit_group;" ::: "memory")
#define CP_WAIT2()   asm volatile("cp.async.wait_group 2;" ::: "memory")
#define CP_WAIT1()   asm volatile("cp.async.wait_group 1;" ::: "memory")
#define CP_WAIT0()   asm volatile("cp.async.wait_group 0;" ::: "memory")

__device__ __forceinline__ void hilo2(float x, float y, uint32_t& hi, uint32_t& lo)
{
    __nv_bfloat16 hx = __float2bfloat16(x), hy = __float2bfloat16(y);
    __nv_bfloat16 lx = __float2bfloat16(x - __bfloat162float(hx));
    __nv_bfloat16 ly = __float2bfloat16(y - __bfloat162float(hy));
    __nv_bfloat162 h2; h2.x = hx; h2.y = hy;
    __nv_bfloat162 l2; l2.x = lx; l2.y = ly;
    hi = *(uint32_t*)&h2;
    lo = *(uint32_t*)&l2;
}

__device__ __forceinline__ void mma16816(float* c, const uint32_t* a, const uint32_t* b)
{
    asm volatile(
        "mma.sync.aligned.m16n8k16.row.col.f32.bf16.bf16.f32 "
        "{%0,%1,%2,%3}, {%4,%5,%6,%7}, {%8,%9}, {%0,%1,%2,%3};"
        : "+f"(c[0]), "+f"(c[1]), "+f"(c[2]), "+f"(c[3])
        : "r"(a[0]), "r"(a[1]), "r"(a[2]), "r"(a[3]), "r"(b[0]), "r"(b[1]));
}

// ---------------------------------------------------------------------------
// Split conversion kernels
// ---------------------------------------------------------------------------
__global__ void split_x_kernel(const float* __restrict__ in,
                               __nv_bfloat16* __restrict__ out)
{
    int idx = blockIdx.x * blockDim.x + threadIdx.x;
    int r = idx >> 10;
    int k = idx & 1023;
    float x = in[idx];
    __nv_bfloat16 hi = __float2bfloat16(x);
    __nv_bfloat16 lo = __float2bfloat16(x - __bfloat162float(hi));
    __nv_bfloat16* o = out + (size_t)r * K3 + k;
    o[0] = hi; o[1024] = hi; o[2048] = lo;
}

__global__ void split_w_kernel(const float* __restrict__ W0, const float* __restrict__ W1,
                               const float* __restrict__ W2, const float* __restrict__ W3,
                               __nv_bfloat16* __restrict__ out)
{
    int w = blockIdx.y;
    const float* in = (w == 0) ? W0 : (w == 1) ? W1 : (w == 2) ? W2 : W3;
    int idx = blockIdx.x * blockDim.x + threadIdx.x;
    int r = idx >> 10;
    int k = idx & 1023;
    float x = in[idx];
    __nv_bfloat16 hi = __float2bfloat16(x);
    __nv_bfloat16 lo = __float2bfloat16(x - __bfloat162float(hi));
    __nv_bfloat16* o = out + (size_t)w * EMB * K3 + (size_t)r * K3 + k;
    o[0] = hi; o[1024] = lo; o[2048] = hi;
}

// ---------------------------------------------------------------------------
// bf16 HMMA GEMM, K=3072, 128x128 tile, 8 warps, 3-stage cp.async pipeline.
// mode 0: fused QKV (grid.x covers N=3072), writes split hi/lo to [B,H,S,D]
// mode 1: O-projection (N=1024), writes fp32 row-major
// ---------------------------------------------------------------------------
#define GPAD   40
#define KCH    32
#define NCHUNK (K3 / KCH)   // 96
#define G_SMEM (2 * 3 * 128 * GPAD * 2)   // 61440 bytes

__global__ void __launch_bounds__(256, 2)
gemm_mma_kernel(const __nv_bfloat16* __restrict__ A,
                const __nv_bfloat16* __restrict__ B,
                const float* __restrict__ bias0, const float* __restrict__ bias1,
                const float* __restrict__ bias2,
                __nv_bfloat16* __restrict__ Qhi, __nv_bfloat16* __restrict__ Qlo,
                __nv_bfloat16* __restrict__ Khi, __nv_bfloat16* __restrict__ Klo,
                __nv_bfloat16* __restrict__ Vhi, __nv_bfloat16* __restrict__ Vlo,
                float* __restrict__ Cf, int mode)
{
    extern __shared__ __nv_bfloat16 smraw[];
    __nv_bfloat16 (*As)[128][GPAD] = reinterpret_cast<__nv_bfloat16(*)[128][GPAD]>(smraw);
    __nv_bfloat16 (*Bs)[128][GPAD] = reinterpret_cast<__nv_bfloat16(*)[128][GPAD]>(smraw + 3 * 128 * GPAD);

    const int tid  = threadIdx.x;
    const int wid  = tid >> 5;
    const int lane = tid & 31;
    const int g    = lane >> 2;
    const int t    = lane & 3;
    const int bm   = blockIdx.y;
    const int bn   = blockIdx.x;
    const int wm   = (wid >> 2) * 64;
    const int wn   = (wid & 3) * 32;

    const int lrow = tid >> 1;          // 0..127
    const int lco  = (tid & 1) * 16;    // 0 or 16
    const __nv_bfloat16* Ag = A + (size_t)(bm * 128 + lrow) * K3 + lco;
    const __nv_bfloat16* Bg = B + (size_t)(bn * 128 + lrow) * K3 + lco;
    const uint32_t dA = smem_u32(&As[0][lrow][lco]);
    const uint32_t dB = smem_u32(&Bs[0][lrow][lco]);
    const uint32_t stg_bytes = 128 * GPAD * 2;

    auto load_st = [&](int st, int k0) {
        CP_ASYNC16(dA + st * stg_bytes,      Ag + k0);
        CP_ASYNC16(dA + st * stg_bytes + 16, Ag + k0 + 8);
        CP_ASYNC16(dB + st * stg_bytes,      Bg + k0);
        CP_ASYNC16(dB + st * stg_bytes + 16, Bg + k0 + 8);
        CP_COMMIT();
    };

    float acc[4][4][4];
#pragma unroll
    for (int i = 0; i < 4; i++)
#pragma unroll
        for (int j = 0; j < 4; j++)
#pragma unroll
            for (int q = 0; q < 4; q++) acc[i][j][q] = 0.f;

    load_st(0, 0);
    load_st(1, KCH);

    for (int c = 0; c < NCHUNK; c++) {
        const int st = c % 3;
        if (c + 2 < NCHUNK) {
            load_st((c + 2) % 3, (c + 2) * KCH);
            CP_WAIT2();
        } else if (c + 1 < NCHUNK) {
            CP_WAIT1();
        } else {
            CP_WAIT0();
        }
        __syncthreads();

#pragma unroll
        for (int kk = 0; kk < KCH; kk += 16) {
            uint32_t af[4][4], bf[4][2];
#pragma unroll
            for (int mi = 0; mi < 4; mi++) {
                const __nv_bfloat16* p = &As[st][wm + mi * 16 + g][kk + 2 * t];
                af[mi][0] = *(const uint32_t*)(p);
                af[mi][1] = *(const uint32_t*)(p + 8 * GPAD);
                af[mi][2] = *(const uint32_t*)(p + 8);
                af[mi][3] = *(const uint32_t*)(p + 8 * GPAD + 8);
            }
#pragma unroll
            for (int ni = 0; ni < 4; ni++) {
                const __nv_bfloat16* p = &Bs[st][wn + ni * 8 + g][kk + 2 * t];
                bf[ni][0] = *(const uint32_t*)(p);
                bf[ni][1] = *(const uint32_t*)(p + 8);
            }
#pragma unroll
            for (int mi = 0; mi < 4; mi++)
#pragma unroll
                for (int ni = 0; ni < 4; ni++)
                    mma16816(acc[mi][ni], af[mi], bf[ni]);
        }
        __syncthreads();
    }

    // epilogue
#pragma unroll
    for (int mi = 0; mi < 4; mi++) {
        const int r0 = bm * 128 + wm + mi * 16 + g;
#pragma unroll
        for (int ni = 0; ni < 4; ni++) {
            const int c = bn * 128 + wn + ni * 8 + 2 * t;
            if (mode == 0) {
                const int which = c >> 10;
                const int cc    = c & 1023;
                const float* bp = (which == 0) ? bias0 : (which == 1) ? bias1 : bias2;
                const float bv0 = bp[cc], bv1 = bp[cc + 1];
                float v00 = acc[mi][ni][0] + bv0, v01 = acc[mi][ni][1] + bv1;
                float v10 = acc[mi][ni][2] + bv0, v11 = acc[mi][ni][3] + bv1;
                const int b = r0 >> 11, sq = r0 & 2047;
                const int h = cc >> 6, d = cc & 63;
                size_t off0 = (((size_t)(b * NHEAD + h) * SEQ) + sq) * HDIM + d;
                size_t off1 = off0 + 8 * HDIM;
                __nv_bfloat16* Hh = (which == 0) ? Qhi : (which == 1) ? Khi : Vhi;
                __nv_bfloat16* Ll = (which == 0) ? Qlo : (which == 1) ? Klo : Vlo;
                uint32_t hi0, lo0, hi1, lo1;
                hilo2(v00, v01, hi0, lo0);
                hilo2(v10, v11, hi1, lo1);
                *(uint32_t*)(Hh + off0) = hi0;
                *(uint32_t*)(Ll + off0) = lo0;
                *(uint32_t*)(Hh + off1) = hi1;
                *(uint32_t*)(Ll + off1) = lo1;
            } else {
                const float bv0 = bias0[c], bv1 = bias0[c + 1];
                *(float2*)(Cf + (size_t)r0 * EMB + c) =
                    make_float2(acc[mi][ni][0] + bv0, acc[mi][ni][1] + bv1);
                *(float2*)(Cf + (size_t)(r0 + 8) * EMB + c) =
                    make_float2(acc[mi][ni][2] + bv0, acc[mi][ni][3] + bv1);
            }
        }
    }
}

// ---------------------------------------------------------------------------
// Tensor-core flash attention, split-bf16 (unchanged, R3-proven).
// ---------------------------------------------------------------------------
#define ASTR 72

__global__ void __launch_bounds__(128)
attn_mma_kernel(const __nv_bfloat16* __restrict__ Qhi, const __nv_bfloat16* __restrict__ Qlo,
                const __nv_bfloat16* __restrict__ Khi, const __nv_bfloat16* __restrict__ Klo,
                const __nv_bfloat16* __restrict__ Vhi, const __nv_bfloat16* __restrict__ Vlo,
                __nv_bfloat16* __restrict__ Out)
{
    __shared__ __nv_bfloat16 sKhi[64][ASTR];
    __shared__ __nv_bfloat16 sKlo[64][ASTR];
    __shared__ __nv_bfloat16 sVhi[64][ASTR];
    __shared__ __nv_bfloat16 sVlo[64][ASTR];

    const int tid  = threadIdx.x;
    const int wid  = tid >> 5;
    const int lane = tid & 31;
    const int g    = lane >> 2;
    const int t    = lane & 3;
    const int qt   = blockIdx.x;
    const int bh   = blockIdx.y;
    const size_t base = (size_t)bh * SEQ * HDIM;

#pragma unroll
    for (int i = 0; i < 4; i++) {
        int idx = tid + 128 * i;
        int row = idx >> 3;
        int co  = (idx & 7) * 8;
        *(uint4*)&sKhi[row][co] = *(const uint4*)&Qhi[base + (size_t)(qt * 64 + row) * HDIM + co];
        *(uint4*)&sKlo[row][co] = *(const uint4*)&Qlo[base + (size_t)(qt * 64 + row) * HDIM + co];
    }
    __syncthreads();

    uint32_t qh[4][4], ql[4][4];
    {
        const int r = wid * 16 + g;
#pragma unroll
        for (int kj = 0; kj < 4; kj++) {
            qh[kj][0] = *(const uint32_t*)&sKhi[r][16 * kj + 2 * t];
            qh[kj][1] = *(const uint32_t*)&sKhi[r + 8][16 * kj + 2 * t];
            qh[kj][2] = *(const uint32_t*)&sKhi[r][16 * kj + 2 * t + 8];
            qh[kj][3] = *(const uint32_t*)&sKhi[r + 8][16 * kj + 2 * t + 8];
            ql[kj][0] = *(const uint32_t*)&sKlo[r][16 * kj + 2 * t];
            ql[kj][1] = *(const uint32_t*)&sKlo[r + 8][16 * kj + 2 * t];
            ql[kj][2] = *(const uint32_t*)&sKlo[r][16 * kj + 2 * t + 8];
            ql[kj][3] = *(const uint32_t*)&sKlo[r + 8][16 * kj + 2 * t + 8];
        }
    }

    float o[8][4];
#pragma unroll
    for (int ni = 0; ni < 8; ni++)
#pragma unroll
        for (int j = 0; j < 4; j++) o[ni][j] = 0.f;
    float m0 = -1e30f, m1 = -1e30f, l0 = 0.f, l1 = 0.f;

    for (int kt = 0; kt < SEQ; kt += 64) {
        __syncthreads();
#pragma unroll
        for (int i = 0; i < 4; i++) {
            int idx = tid + 128 * i;
            int row = idx >> 3;
            int co  = (idx & 7) * 8;
            *(uint4*)&sKhi[row][co] = *(const uint4*)&Khi[base + (size_t)(kt + row) * HDIM + co];
            *(uint4*)&sKlo[row][co] = *(const uint4*)&Klo[base + (size_t)(kt + row) * HDIM + co];
        }
#pragma unroll
        for (int it = 0; it < 2; it++) {
            int idx = tid + 128 * it;
            int rp  = idx & 31;
            int cg  = (idx >> 5) * 8;
            uint4 h0 = *(const uint4*)&Vhi[base + (size_t)(kt + 2 * rp) * HDIM + cg];
            uint4 h1 = *(const uint4*)&Vhi[base + (size_t)(kt + 2 * rp + 1) * HDIM + cg];
            uint4 w0 = *(const uint4*)&Vlo[base + (size_t)(kt + 2 * rp) * HDIM + cg];
            uint4 w1 = *(const uint4*)&Vlo[base + (size_t)(kt + 2 * rp + 1) * HDIM + cg];
            const __nv_bfloat16* a0 = (const __nv_bfloat16*)&h0;
            const __nv_bfloat16* a1 = (const __nv_bfloat16*)&h1;
            const __nv_bfloat16* c0 = (const __nv_bfloat16*)&w0;
            const __nv_bfloat16* c1 = (const __nv_bfloat16*)&w1;
#pragma unroll
            for (int e = 0; e < 8; e++) {
                __nv_bfloat162 ph; ph.x = a0[e]; ph.y = a1[e];
                __nv_bfloat162 pl; pl.x = c0[e]; pl.y = c1[e];
                *(uint32_t*)&sVhi[cg + e][2 * rp] = *(uint32_t*)&ph;
                *(uint32_t*)&sVlo[cg + e][2 * rp] = *(uint32_t*)&pl;
            }
        }
        __syncthreads();

        float sc[8][4];
#pragma unroll
        for (int ni = 0; ni < 8; ni++)
#pragma unroll
            for (int j = 0; j < 4; j++) sc[ni][j] = 0.f;

#pragma unroll
        for (int kj = 0; kj < 4; kj++) {
#pragma unroll
            for (int ni = 0; ni < 8; ni++) {
                uint32_t bh_[2], bl_[2];
                bh_[0] = *(const uint32_t*)&sKhi[8 * ni + g][16 * kj + 2 * t];
                bh_[1] = *(const uint32_t*)&sKhi[8 * ni + g][16 * kj + 2 * t + 8];
                bl_[0] = *(const uint32_t*)&sKlo[8 * ni + g][16 * kj + 2 * t];
                bl_[1] = *(const uint32_t*)&sKlo[8 * ni + g][16 * kj + 2 * t + 8];
                mma16816(sc[ni], qh[kj], bh_);
                mma16816(sc[ni], qh[kj], bl_);
                mma16816(sc[ni], ql[kj], bh_);
            }
        }

        float mx0 = -1e30f, mx1 = -1e30f;
#pragma unroll
        for (int ni = 0; ni < 8; ni++) {
            sc[ni][0] *= 0.125f; sc[ni][1] *= 0.125f;
            sc[ni][2] *= 0.125f; sc[ni][3] *= 0.125f;
            mx0 = fmaxf(mx0, fmaxf(sc[ni][0], sc[ni][1]));
            mx1 = fmaxf(mx1, fmaxf(sc[ni][2], sc[ni][3]));
        }
        mx0 = fmaxf(mx0, __shfl_xor_sync(0xffffffff, mx0, 1));
        mx0 = fmaxf(mx0, __shfl_xor_sync(0xffffffff, mx0, 2));
        mx1 = fmaxf(mx1, __shfl_xor_sync(0xffffffff, mx1, 1));
        mx1 = fmaxf(mx1, __shfl_xor_sync(0xffffffff, mx1, 2));

        const float nm0 = fmaxf(m0, mx0);
        const float nm1 = fmaxf(m1, mx1);
        const float rs0 = __expf(m0 - nm0);
        const float rs1 = __expf(m1 - nm1);
        m0 = nm0; m1 = nm1;
        l0 *= rs0; l1 *= rs1;
#pragma unroll
        for (int ni = 0; ni < 8; ni++) {
            o[ni][0] *= rs0; o[ni][1] *= rs0;
            o[ni][2] *= rs1; o[ni][3] *= rs1;
            sc[ni][0] = __expf(sc[ni][0] - m0);
            sc[ni][1] = __expf(sc[ni][1] - m0);
            sc[ni][2] = __expf(sc[ni][2] - m1);
            sc[ni][3] = __expf(sc[ni][3] - m1);
            l0 += sc[ni][0] + sc[ni][1];
            l1 += sc[ni][2] + sc[ni][3];
        }

#pragma unroll
        for (int kj = 0; kj < 4; kj++) {
            uint32_t ah[4], al[4];
            hilo2(sc[2 * kj][0],     sc[2 * kj][1],     ah[0], al[0]);
            hilo2(sc[2 * kj][2],     sc[2 * kj][3],     ah[1], al[1]);
            hilo2(sc[2 * kj + 1][0], sc[2 * kj + 1][1], ah[2], al[2]);
            hilo2(sc[2 * kj + 1][2], sc[2 * kj + 1][3], ah[3], al[3]);
#pragma unroll
            for (int ni = 0; ni < 8; ni++) {
                uint32_t bh_[2], bl_[2];
                bh_[0] = *(const uint32_t*)&sVhi[8 * ni + g][16 * kj + 2 * t];
                bh_[1] = *(const uint32_t*)&sVhi[8 * ni + g][16 * kj + 2 * t + 8];
                bl_[0] = *(const uint32_t*)&sVlo[8 * ni + g][16 * kj + 2 * t];
                bl_[1] = *(const uint32_t*)&sVlo[8 * ni + g][16 * kj + 2 * t + 8];
                mma16816(o[ni], ah, bh_);
                mma16816(o[ni], ah, bl_);
                mma16816(o[ni], al, bh_);
            }
        }
    }

    l0 += __shfl_xor_sync(0xffffffff, l0, 1);
    l0 += __shfl_xor_sync(0xffffffff, l0, 2);
    l1 += __shfl_xor_sync(0xffffffff, l1, 1);
    l1 += __shfl_xor_sync(0xffffffff, l1, 2);
    const float inv0 = 1.f / l0;
    const float inv1 = 1.f / l1;

    const int s0 = qt * 64 + wid * 16 + g;
    const int b  = bh >> 4;
    const int h  = bh & 15;
    const size_t row0 = (size_t)(b * SEQ + s0) * K3;
    const size_t row1 = row0 + (size_t)8 * K3;

#pragma unroll
    for (int ni = 0; ni < 8; ni++) {
        const int col = h * 64 + 8 * ni + 2 * t;
        uint32_t hi0, lo0, hi1, lo1;
        hilo2(o[ni][0] * inv0, o[ni][1] * inv0, hi0, lo0);
        hilo2(o[ni][2] * inv1, o[ni][3] * inv1, hi1, lo1);
        *(uint32_t*)&Out[row0 + col]        = hi0;
        *(uint32_t*)&Out[row0 + col + 1024] = hi0;
        *(uint32_t*)&Out[row0 + col + 2048] = lo0;
        *(uint32_t*)&Out[row1 + col]        = hi1;
        *(uint32_t*)&Out[row1 + col + 1024] = hi1;
        *(uint32_t*)&Out[row1 + col + 2048] = lo1;
    }
}

// ---------------------------------------------------------------------------
extern "C" void kernel_launch(void* const* d_in, const int* in_sizes, int n_in,
                              void* d_out, int out_size)
{
    const float* X   = (const float*)d_in[0];
    const float* W_q = (const float*)d_in[1];
    const float* b_q = (const float*)d_in[2];
    const float* W_k = (const float*)d_in[3];
    const float* b_k = (const float*)d_in[4];
    const float* W_v = (const float*)d_in[5];
    const float* b_v = (const float*)d_in[6];
    const float* W_o = (const float*)d_in[7];
    const float* b_o = (const float*)d_in[8];
    float* out = (float*)d_out;

    __nv_bfloat16 *Qhi, *Qlo, *Khi, *Klo, *Vhi, *Vlo, *Xs, *Ws, *As;
    cudaGetSymbolAddress((void**)&Qhi, g_Qhi);
    cudaGetSymbolAddress((void**)&Qlo, g_Qlo);
    cudaGetSymbolAddress((void**)&Khi, g_Khi);
    cudaGetSymbolAddress((void**)&Klo, g_Klo);
    cudaGetSymbolAddress((void**)&Vhi, g_Vhi);
    cudaGetSymbolAddress((void**)&Vlo, g_Vlo);
    cudaGetSymbolAddress((void**)&Xs, g_Xs);
    cudaGetSymbolAddress((void**)&Ws, g_Ws);
    cudaGetSymbolAddress((void**)&As, g_As);

    cudaFuncSetAttribute(gemm_mma_kernel, cudaFuncAttributeMaxDynamicSharedMemorySize, G_SMEM);

    const int cthr = 256;
    split_x_kernel<<<MROWS * EMB / cthr, cthr>>>(X, Xs);
    dim3 wgrid(EMB * EMB / cthr, 4);
    split_w_kernel<<<wgrid, cthr>>>(W_q, W_k, W_v, W_o, Ws);

    // fused QKV: N = 3072 (weights q,k,v contiguous in Ws)
    dim3 qkvgrid(K3 / 128, MROWS / 128);   // (24, 32)
    gemm_mma_kernel<<<qkvgrid, 256, G_SMEM>>>(Xs, Ws, b_q, b_k, b_v,
                                              Qhi, Qlo, Khi, Klo, Vhi, Vlo, nullptr, 0);

    dim3 agrid(SEQ / 64, BATCH * NHEAD);
    attn_mma_kernel<<<agrid, 128>>>(Qhi, Qlo, Khi, Klo, Vhi, Vlo, As);

    // O-projection: N = 1024
    dim3 ogrid(EMB / 128, MROWS / 128);    // (8, 32)
    gemm_mma_kernel<<<ogrid, 256, G_SMEM>>>(As, Ws + 3 * (size_t)EMB * K3, b_o, nullptr, nullptr,
                                            nullptr, nullptr, nullptr, nullptr, nullptr, nullptr,
                                            out, 1);
}

// round 6
// speedup vs baseline: 2.7564x; 1.1944x over previous
#include <cuda_runtime.h>
#include <cuda_bf16.h>
#include <stdint.h>
#include <math.h>

#define BATCH   2
#define SEQ     2048
#define EMB     1024
#define NHEAD   16
#define HDIM    64
#define MROWS   (BATCH * SEQ)
#define K3      (3 * EMB)
#define QKV_ELEMS (BATCH * NHEAD * SEQ * HDIM)

// Scratch (__device__ globals)
__device__ __nv_bfloat16 g_Qhi[QKV_ELEMS];
__device__ __nv_bfloat16 g_Qlo[QKV_ELEMS];
__device__ __nv_bfloat16 g_Khi[QKV_ELEMS];
__device__ __nv_bfloat16 g_Klo[QKV_ELEMS];
__device__ __nv_bfloat16 g_Vhi[QKV_ELEMS];
__device__ __nv_bfloat16 g_Vlo[QKV_ELEMS];
__device__ __nv_bfloat16 g_VThi[QKV_ELEMS];   // [B,H,D,S]
__device__ __nv_bfloat16 g_VTlo[QKV_ELEMS];
__device__ __nv_bfloat16 g_Xs[(size_t)MROWS * K3];
__device__ __nv_bfloat16 g_Ws[4][(size_t)EMB * K3];
__device__ __nv_bfloat16 g_As[(size_t)MROWS * K3];

// ---------------------------------------------------------------------------
__device__ __forceinline__ uint32_t smem_u32(const void* p) {
    uint32_t a;
    asm("{ .reg .u64 t; cvta.to.shared.u64 t, %1; cvt.u32.u64 %0, t; }" : "=r"(a) : "l"(p));
    return a;
}
#define CP_ASYNC16(dst, src) asm volatile("cp.async.cg.shared.global [%0], [%1], 16;" :: "r"(dst), "l"(src))
#define CP_COMMIT()  asm volatile("cp.async.commit_group;" ::: "memory")
#define CP_WAIT2()   asm volatile("cp.async.wait_group 2;" ::: "memory")
#define CP_WAIT1()   asm volatile("cp.async.wait_group 1;" ::: "memory")
#define CP_WAIT0()   asm volatile("cp.async.wait_group 0;" ::: "memory")

__device__ __forceinline__ void hilo2(float x, float y, uint32_t& hi, uint32_t& lo)
{
    __nv_bfloat16 hx = __float2bfloat16(x), hy = __float2bfloat16(y);
    __nv_bfloat16 lx = __float2bfloat16(x - __bfloat162float(hx));
    __nv_bfloat16 ly = __float2bfloat16(y - __bfloat162float(hy));
    __nv_bfloat162 h2; h2.x = hx; h2.y = hy;
    __nv_bfloat162 l2; l2.x = lx; l2.y = ly;
    hi = *(uint32_t*)&h2;
    lo = *(uint32_t*)&l2;
}

__device__ __forceinline__ void mma16816(float* c, const uint32_t* a, const uint32_t* b)
{
    asm volatile(
        "mma.sync.aligned.m16n8k16.row.col.f32.bf16.bf16.f32 "
        "{%0,%1,%2,%3}, {%4,%5,%6,%7}, {%8,%9}, {%0,%1,%2,%3};"
        : "+f"(c[0]), "+f"(c[1]), "+f"(c[2]), "+f"(c[3])
        : "r"(a[0]), "r"(a[1]), "r"(a[2]), "r"(a[3]), "r"(b[0]), "r"(b[1]));
}

// ---------------------------------------------------------------------------
// Split conversion kernels
// ---------------------------------------------------------------------------
__global__ void split_x_kernel(const float* __restrict__ in,
                               __nv_bfloat16* __restrict__ out)
{
    int idx = blockIdx.x * blockDim.x + threadIdx.x;
    int r = idx >> 10;
    int k = idx & 1023;
    float x = in[idx];
    __nv_bfloat16 hi = __float2bfloat16(x);
    __nv_bfloat16 lo = __float2bfloat16(x - __bfloat162float(hi));
    __nv_bfloat16* o = out + (size_t)r * K3 + k;
    o[0] = hi; o[1024] = hi; o[2048] = lo;
}

__global__ void split_w_kernel(const float* __restrict__ W0, const float* __restrict__ W1,
                               const float* __restrict__ W2, const float* __restrict__ W3,
                               __nv_bfloat16* __restrict__ out)
{
    int w = blockIdx.y;
    const float* in = (w == 0) ? W0 : (w == 1) ? W1 : (w == 2) ? W2 : W3;
    int idx = blockIdx.x * blockDim.x + threadIdx.x;
    int r = idx >> 10;
    int k = idx & 1023;
    float x = in[idx];
    __nv_bfloat16 hi = __float2bfloat16(x);
    __nv_bfloat16 lo = __float2bfloat16(x - __bfloat162float(hi));
    __nv_bfloat16* o = out + (size_t)w * EMB * K3 + (size_t)r * K3 + k;
    o[0] = hi; o[1024] = lo; o[2048] = hi;
}

// ---------------------------------------------------------------------------
// V transpose: [B,H,S,D] -> [B,H,D,S] for hi and lo, via smem tiles.
// grid (SEQ/64, B*H), block 256.
// ---------------------------------------------------------------------------
__global__ void __launch_bounds__(256)
transpose_v_kernel(const __nv_bfloat16* __restrict__ Vhi, const __nv_bfloat16* __restrict__ Vlo,
                   __nv_bfloat16* __restrict__ VThi, __nv_bfloat16* __restrict__ VTlo)
{
    __shared__ __nv_bfloat16 t0[64][72];
    __shared__ __nv_bfloat16 t1[64][72];
    const int tid = threadIdx.x;
    const int st  = blockIdx.x * 64;
    const int bh  = blockIdx.y;
    const size_t bi = (size_t)bh * SEQ * HDIM;
    const size_t bo = (size_t)bh * HDIM * SEQ;

#pragma unroll
    for (int j = 0; j < 2; j++) {
        int id  = tid + j * 256;
        int row = id >> 3;            // token in tile
        int co  = (id & 7) * 8;       // d
        *(uint4*)&t0[row][co] = *(const uint4*)&Vhi[bi + (size_t)(st + row) * HDIM + co];
        *(uint4*)&t1[row][co] = *(const uint4*)&Vlo[bi + (size_t)(st + row) * HDIM + co];
    }
    __syncthreads();

#pragma unroll
    for (int j = 0; j < 2; j++) {
        int id  = tid + j * 256;
        int d   = id >> 3;            // d row
        int co  = (id & 7) * 8;       // token offset
        __nv_bfloat16 h[8], l[8];
#pragma unroll
        for (int e = 0; e < 8; e++) { h[e] = t0[co + e][d]; l[e] = t1[co + e][d]; }
        *(uint4*)&VThi[bo + (size_t)d * SEQ + st + co] = *(uint4*)h;
        *(uint4*)&VTlo[bo + (size_t)d * SEQ + st + co] = *(uint4*)l;
    }
}

// ---------------------------------------------------------------------------
// bf16 HMMA GEMM, K=3072, 128x128 tile, 8 warps, 3-stage cp.async (R5-proven).
// ---------------------------------------------------------------------------
#define GPAD   40
#define KCH    32
#define NCHUNK (K3 / KCH)
#define G_SMEM (2 * 3 * 128 * GPAD * 2)

__global__ void __launch_bounds__(256, 2)
gemm_mma_kernel(const __nv_bfloat16* __restrict__ A,
                const __nv_bfloat16* __restrict__ B,
                const float* __restrict__ bias0, const float* __restrict__ bias1,
                const float* __restrict__ bias2,
                __nv_bfloat16* __restrict__ Qhi, __nv_bfloat16* __restrict__ Qlo,
                __nv_bfloat16* __restrict__ Khi, __nv_bfloat16* __restrict__ Klo,
                __nv_bfloat16* __restrict__ Vhi, __nv_bfloat16* __restrict__ Vlo,
                float* __restrict__ Cf, int mode)
{
    extern __shared__ __nv_bfloat16 smraw[];
    __nv_bfloat16 (*As)[128][GPAD] = reinterpret_cast<__nv_bfloat16(*)[128][GPAD]>(smraw);
    __nv_bfloat16 (*Bs)[128][GPAD] = reinterpret_cast<__nv_bfloat16(*)[128][GPAD]>(smraw + 3 * 128 * GPAD);

    const int tid  = threadIdx.x;
    const int wid  = tid >> 5;
    const int lane = tid & 31;
    const int g    = lane >> 2;
    const int t    = lane & 3;
    const int bm   = blockIdx.y;
    const int bn   = blockIdx.x;
    const int wm   = (wid >> 2) * 64;
    const int wn   = (wid & 3) * 32;

    const int lrow = tid >> 1;
    const int lco  = (tid & 1) * 16;
    const __nv_bfloat16* Ag = A + (size_t)(bm * 128 + lrow) * K3 + lco;
    const __nv_bfloat16* Bg = B + (size_t)(bn * 128 + lrow) * K3 + lco;
    const uint32_t dA = smem_u32(&As[0][lrow][lco]);
    const uint32_t dB = smem_u32(&Bs[0][lrow][lco]);
    const uint32_t stg_bytes = 128 * GPAD * 2;

    auto load_st = [&](int st, int k0) {
        CP_ASYNC16(dA + st * stg_bytes,      Ag + k0);
        CP_ASYNC16(dA + st * stg_bytes + 16, Ag + k0 + 8);
        CP_ASYNC16(dB + st * stg_bytes,      Bg + k0);
        CP_ASYNC16(dB + st * stg_bytes + 16, Bg + k0 + 8);
        CP_COMMIT();
    };

    float acc[4][4][4];
#pragma unroll
    for (int i = 0; i < 4; i++)
#pragma unroll
        for (int j = 0; j < 4; j++)
#pragma unroll
            for (int q = 0; q < 4; q++) acc[i][j][q] = 0.f;

    load_st(0, 0);
    load_st(1, KCH);

    for (int c = 0; c < NCHUNK; c++) {
        const int st = c % 3;
        if (c + 2 < NCHUNK) { load_st((c + 2) % 3, (c + 2) * KCH); CP_WAIT2(); }
        else if (c + 1 < NCHUNK) { CP_WAIT1(); }
        else { CP_WAIT0(); }
        __syncthreads();

#pragma unroll
        for (int kk = 0; kk < KCH; kk += 16) {
            uint32_t af[4][4], bf[4][2];
#pragma unroll
            for (int mi = 0; mi < 4; mi++) {
                const __nv_bfloat16* p = &As[st][wm + mi * 16 + g][kk + 2 * t];
                af[mi][0] = *(const uint32_t*)(p);
                af[mi][1] = *(const uint32_t*)(p + 8 * GPAD);
                af[mi][2] = *(const uint32_t*)(p + 8);
                af[mi][3] = *(const uint32_t*)(p + 8 * GPAD + 8);
            }
#pragma unroll
            for (int ni = 0; ni < 4; ni++) {
                const __nv_bfloat16* p = &Bs[st][wn + ni * 8 + g][kk + 2 * t];
                bf[ni][0] = *(const uint32_t*)(p);
                bf[ni][1] = *(const uint32_t*)(p + 8);
            }
#pragma unroll
            for (int mi = 0; mi < 4; mi++)
#pragma unroll
                for (int ni = 0; ni < 4; ni++)
                    mma16816(acc[mi][ni], af[mi], bf[ni]);
        }
        __syncthreads();
    }

#pragma unroll
    for (int mi = 0; mi < 4; mi++) {
        const int r0 = bm * 128 + wm + mi * 16 + g;
#pragma unroll
        for (int ni = 0; ni < 4; ni++) {
            const int c = bn * 128 + wn + ni * 8 + 2 * t;
            if (mode == 0) {
                const int which = c >> 10;
                const int cc    = c & 1023;
                const float* bp = (which == 0) ? bias0 : (which == 1) ? bias1 : bias2;
                const float bv0 = bp[cc], bv1 = bp[cc + 1];
                float v00 = acc[mi][ni][0] + bv0, v01 = acc[mi][ni][1] + bv1;
                float v10 = acc[mi][ni][2] + bv0, v11 = acc[mi][ni][3] + bv1;
                const int b = r0 >> 11, sq = r0 & 2047;
                const int h = cc >> 6, d = cc & 63;
                size_t off0 = (((size_t)(b * NHEAD + h) * SEQ) + sq) * HDIM + d;
                size_t off1 = off0 + 8 * HDIM;
                __nv_bfloat16* Hh = (which == 0) ? Qhi : (which == 1) ? Khi : Vhi;
                __nv_bfloat16* Ll = (which == 0) ? Qlo : (which == 1) ? Klo : Vlo;
                uint32_t hi0, lo0, hi1, lo1;
                hilo2(v00, v01, hi0, lo0);
                hilo2(v10, v11, hi1, lo1);
                *(uint32_t*)(Hh + off0) = hi0;
                *(uint32_t*)(Ll + off0) = lo0;
                *(uint32_t*)(Hh + off1) = hi1;
                *(uint32_t*)(Ll + off1) = lo1;
            } else {
                const float bv0 = bias0[c], bv1 = bias0[c + 1];
                *(float2*)(Cf + (size_t)r0 * EMB + c) =
                    make_float2(acc[mi][ni][0] + bv0, acc[mi][ni][1] + bv1);
                *(float2*)(Cf + (size_t)(r0 + 8) * EMB + c) =
                    make_float2(acc[mi][ni][2] + bv0, acc[mi][ni][3] + bv1);
            }
        }
    }
}

// ---------------------------------------------------------------------------
// Tensor-core flash attention v2: cp.async double-buffered K/V^T staging.
// Block 128 threads (4 warps), Br=64, Bc=64, grid (SEQ/64, B*H).
// ---------------------------------------------------------------------------
#define ASTR 72
#define A_STG (64 * ASTR)                 // bf16 elems per array per stage
#define ATT_SMEM (8 * A_STG * 2)          // 8 arrays (2 stages x hi/lo x K,VT), 73728 B

__global__ void __launch_bounds__(128, 3)
attn_mma_kernel(const __nv_bfloat16* __restrict__ Qhi, const __nv_bfloat16* __restrict__ Qlo,
                const __nv_bfloat16* __restrict__ Khi, const __nv_bfloat16* __restrict__ Klo,
                const __nv_bfloat16* __restrict__ VThi, const __nv_bfloat16* __restrict__ VTlo,
                __nv_bfloat16* __restrict__ Out)
{
    extern __shared__ __nv_bfloat16 sm[];
    // layout: K[stage][hl] at ((st*2+hl))*A_STG ; VT[stage][hl] at 4*A_STG + ...
    __nv_bfloat16* sK  = sm;
    __nv_bfloat16* sVT = sm + 4 * A_STG;

    const int tid  = threadIdx.x;
    const int wid  = tid >> 5;
    const int lane = tid & 31;
    const int g    = lane >> 2;
    const int t    = lane & 3;
    const int qt   = blockIdx.x;
    const int bh   = blockIdx.y;
    const size_t base  = (size_t)bh * SEQ * HDIM;   // K layout [s][d]
    const size_t baseT = (size_t)bh * HDIM * SEQ;   // VT layout [d][s]

    // --- Stage Q tile into sK stage 0 (plain loads), extract frags ---
#pragma unroll
    for (int i = 0; i < 4; i++) {
        int idx = tid + 128 * i;
        int row = idx >> 3;
        int co  = (idx & 7) * 8;
        *(uint4*)&sK[row * ASTR + co]         = *(const uint4*)&Qhi[base + (size_t)(qt * 64 + row) * HDIM + co];
        *(uint4*)&sK[A_STG + row * ASTR + co] = *(const uint4*)&Qlo[base + (size_t)(qt * 64 + row) * HDIM + co];
    }
    __syncthreads();

    uint32_t qh[4][4], ql[4][4];
    {
        const int r = wid * 16 + g;
#pragma unroll
        for (int kj = 0; kj < 4; kj++) {
            const __nv_bfloat16* ph = &sK[r * ASTR + 16 * kj + 2 * t];
            const __nv_bfloat16* pl = &sK[A_STG + r * ASTR + 16 * kj + 2 * t];
            qh[kj][0] = *(const uint32_t*)(ph);
            qh[kj][1] = *(const uint32_t*)(ph + 8 * ASTR);
            qh[kj][2] = *(const uint32_t*)(ph + 8);
            qh[kj][3] = *(const uint32_t*)(ph + 8 * ASTR + 8);
            ql[kj][0] = *(const uint32_t*)(pl);
            ql[kj][1] = *(const uint32_t*)(pl + 8 * ASTR);
            ql[kj][2] = *(const uint32_t*)(pl + 8);
            ql[kj][3] = *(const uint32_t*)(pl + 8 * ASTR + 8);
        }
    }
    __syncthreads();

    // cp.async staging of one stage: K hi/lo rows=token, VT hi/lo rows=d
    const uint32_t sKa  = smem_u32(sK);
    const uint32_t sVTa = smem_u32(sVT);
    auto stage = [&](int st, int kt) {
#pragma unroll
        for (int j = 0; j < 4; j++) {
            int id  = tid + 128 * j;
            int row = id >> 3;
            int co  = (id & 7) * 8;
            uint32_t so = ((uint32_t)row * ASTR + co) * 2;
            CP_ASYNC16(sKa  + (st * 2 + 0) * A_STG * 2 + so, Khi  + base  + (size_t)(kt + row) * HDIM + co);
            CP_ASYNC16(sKa  + (st * 2 + 1) * A_STG * 2 + so, Klo  + base  + (size_t)(kt + row) * HDIM + co);
            CP_ASYNC16(sVTa + (st * 2 + 0) * A_STG * 2 + so, VThi + baseT + (size_t)row * SEQ + kt + co);
            CP_ASYNC16(sVTa + (st * 2 + 1) * A_STG * 2 + so, VTlo + baseT + (size_t)row * SEQ + kt + co);
        }
        CP_COMMIT();
    };

    float o[8][4];
#pragma unroll
    for (int ni = 0; ni < 8; ni++)
#pragma unroll
        for (int j = 0; j < 4; j++) o[ni][j] = 0.f;
    float m0 = -1e30f, m1 = -1e30f, l0 = 0.f, l1 = 0.f;

    stage(0, 0);
    stage(1, 64);

    const int NT = SEQ / 64;
    for (int it = 0; it < NT; it++) {
        const int s = it & 1;
        if (it + 1 < NT) { CP_WAIT1(); } else { CP_WAIT0(); }
        __syncthreads();

        const __nv_bfloat16* cKhi  = sK  + (s * 2 + 0) * A_STG;
        const __nv_bfloat16* cKlo  = sK  + (s * 2 + 1) * A_STG;
        const __nv_bfloat16* cVhi  = sVT + (s * 2 + 0) * A_STG;
        const __nv_bfloat16* cVlo  = sVT + (s * 2 + 1) * A_STG;

        // --- S = Q K^T (3 split terms) ---
        float sc[8][4];
#pragma unroll
        for (int ni = 0; ni < 8; ni++)
#pragma unroll
            for (int j = 0; j < 4; j++) sc[ni][j] = 0.f;

#pragma unroll
        for (int kj = 0; kj < 4; kj++) {
#pragma unroll
            for (int ni = 0; ni < 8; ni++) {
                const __nv_bfloat16* ph = &cKhi[(8 * ni + g) * ASTR + 16 * kj + 2 * t];
                const __nv_bfloat16* pl = &cKlo[(8 * ni + g) * ASTR + 16 * kj + 2 * t];
                uint32_t bh_[2], bl_[2];
                bh_[0] = *(const uint32_t*)(ph);
                bh_[1] = *(const uint32_t*)(ph + 8);
                bl_[0] = *(const uint32_t*)(pl);
                bl_[1] = *(const uint32_t*)(pl + 8);
                mma16816(sc[ni], qh[kj], bh_);
                mma16816(sc[ni], qh[kj], bl_);
                mma16816(sc[ni], ql[kj], bh_);
            }
        }

        // --- online softmax ---
        float mx0 = -1e30f, mx1 = -1e30f;
#pragma unroll
        for (int ni = 0; ni < 8; ni++) {
            sc[ni][0] *= 0.125f; sc[ni][1] *= 0.125f;
            sc[ni][2] *= 0.125f; sc[ni][3] *= 0.125f;
            mx0 = fmaxf(mx0, fmaxf(sc[ni][0], sc[ni][1]));
            mx1 = fmaxf(mx1, fmaxf(sc[ni][2], sc[ni][3]));
        }
        mx0 = fmaxf(mx0, __shfl_xor_sync(0xffffffff, mx0, 1));
        mx0 = fmaxf(mx0, __shfl_xor_sync(0xffffffff, mx0, 2));
        mx1 = fmaxf(mx1, __shfl_xor_sync(0xffffffff, mx1, 1));
        mx1 = fmaxf(mx1, __shfl_xor_sync(0xffffffff, mx1, 2));

        const float nm0 = fmaxf(m0, mx0);
        const float nm1 = fmaxf(m1, mx1);
        const float rs0 = __expf(m0 - nm0);
        const float rs1 = __expf(m1 - nm1);
        m0 = nm0; m1 = nm1;
        l0 *= rs0; l1 *= rs1;
#pragma unroll
        for (int ni = 0; ni < 8; ni++) {
            o[ni][0] *= rs0; o[ni][1] *= rs0;
            o[ni][2] *= rs1; o[ni][3] *= rs1;
            sc[ni][0] = __expf(sc[ni][0] - m0);
            sc[ni][1] = __expf(sc[ni][1] - m0);
            sc[ni][2] = __expf(sc[ni][2] - m1);
            sc[ni][3] = __expf(sc[ni][3] - m1);
            l0 += sc[ni][0] + sc[ni][1];
            l1 += sc[ni][2] + sc[ni][3];
        }

        // --- O += P V (3 split terms) ---
#pragma unroll
        for (int kj = 0; kj < 4; kj++) {
            uint32_t ah[4], al[4];
            hilo2(sc[2 * kj][0],     sc[2 * kj][1],     ah[0], al[0]);
            hilo2(sc[2 * kj][2],     sc[2 * kj][3],     ah[1], al[1]);
            hilo2(sc[2 * kj + 1][0], sc[2 * kj + 1][1], ah[2], al[2]);
            hilo2(sc[2 * kj + 1][2], sc[2 * kj + 1][3], ah[3], al[3]);
#pragma unroll
            for (int ni = 0; ni < 8; ni++) {
                const __nv_bfloat16* ph = &cVhi[(8 * ni + g) * ASTR + 16 * kj + 2 * t];
                const __nv_bfloat16* pl = &cVlo[(8 * ni + g) * ASTR + 16 * kj + 2 * t];
                uint32_t bh_[2], bl_[2];
                bh_[0] = *(const uint32_t*)(ph);
                bh_[1] = *(const uint32_t*)(ph + 8);
                bl_[0] = *(const uint32_t*)(pl);
                bl_[1] = *(const uint32_t*)(pl + 8);
                mma16816(o[ni], ah, bh_);
                mma16816(o[ni], ah, bl_);
                mma16816(o[ni], al, bh_);
            }
        }

        __syncthreads();
        if (it + 2 < NT) stage(s, (it + 2) * 64);
    }

    // --- finalize ---
    l0 += __shfl_xor_sync(0xffffffff, l0, 1);
    l0 += __shfl_xor_sync(0xffffffff, l0, 2);
    l1 += __shfl_xor_sync(0xffffffff, l1, 1);
    l1 += __shfl_xor_sync(0xffffffff, l1, 2);
    const float inv0 = 1.f / l0;
    const float inv1 = 1.f / l1;

    const int s0 = qt * 64 + wid * 16 + g;
    const int b  = bh >> 4;
    const int h  = bh & 15;
    const size_t row0 = (size_t)(b * SEQ + s0) * K3;
    const size_t row1 = row0 + (size_t)8 * K3;

#pragma unroll
    for (int ni = 0; ni < 8; ni++) {
        const int col = h * 64 + 8 * ni + 2 * t;
        uint32_t hi0, lo0, hi1, lo1;
        hilo2(o[ni][0] * inv0, o[ni][1] * inv0, hi0, lo0);
        hilo2(o[ni][2] * inv1, o[ni][3] * inv1, hi1, lo1);
        *(uint32_t*)&Out[row0 + col]        = hi0;
        *(uint32_t*)&Out[row0 + col + 1024] = hi0;
        *(uint32_t*)&Out[row0 + col + 2048] = lo0;
        *(uint32_t*)&Out[row1 + col]        = hi1;
        *(uint32_t*)&Out[row1 + col + 1024] = hi1;
        *(uint32_t*)&Out[row1 + col + 2048] = lo1;
    }
}

// ---------------------------------------------------------------------------
extern "C" void kernel_launch(void* const* d_in, const int* in_sizes, int n_in,
                              void* d_out, int out_size)
{
    const float* X   = (const float*)d_in[0];
    const float* W_q = (const float*)d_in[1];
    const float* b_q = (const float*)d_in[2];
    const float* W_k = (const float*)d_in[3];
    const float* b_k = (const float*)d_in[4];
    const float* W_v = (const float*)d_in[5];
    const float* b_v = (const float*)d_in[6];
    const float* W_o = (const float*)d_in[7];
    const float* b_o = (const float*)d_in[8];
    float* out = (float*)d_out;

    __nv_bfloat16 *Qhi, *Qlo, *Khi, *Klo, *Vhi, *Vlo, *VThi, *VTlo, *Xs, *Ws, *As;
    cudaGetSymbolAddress((void**)&Qhi, g_Qhi);
    cudaGetSymbolAddress((void**)&Qlo, g_Qlo);
    cudaGetSymbolAddress((void**)&Khi, g_Khi);
    cudaGetSymbolAddress((void**)&Klo, g_Klo);
    cudaGetSymbolAddress((void**)&Vhi, g_Vhi);
    cudaGetSymbolAddress((void**)&Vlo, g_Vlo);
    cudaGetSymbolAddress((void**)&VThi, g_VThi);
    cudaGetSymbolAddress((void**)&VTlo, g_VTlo);
    cudaGetSymbolAddress((void**)&Xs, g_Xs);
    cudaGetSymbolAddress((void**)&Ws, g_Ws);
    cudaGetSymbolAddress((void**)&As, g_As);

    cudaFuncSetAttribute(gemm_mma_kernel, cudaFuncAttributeMaxDynamicSharedMemorySize, G_SMEM);
    cudaFuncSetAttribute(attn_mma_kernel, cudaFuncAttributeMaxDynamicSharedMemorySize, ATT_SMEM);

    const int cthr = 256;
    split_x_kernel<<<MROWS * EMB / cthr, cthr>>>(X, Xs);
    dim3 wgrid(EMB * EMB / cthr, 4);
    split_w_kernel<<<wgrid, cthr>>>(W_q, W_k, W_v, W_o, Ws);

    dim3 qkvgrid(K3 / 128, MROWS / 128);
    gemm_mma_kernel<<<qkvgrid, 256, G_SMEM>>>(Xs, Ws, b_q, b_k, b_v,
                                              Qhi, Qlo, Khi, Klo, Vhi, Vlo, nullptr, 0);

    dim3 tgrid(SEQ / 64, BATCH * NHEAD);
    transpose_v_kernel<<<tgrid, 256>>>(Vhi, Vlo, VThi, VTlo);

    dim3 agrid(SEQ / 64, BATCH * NHEAD);
    attn_mma_kernel<<<agrid, 128, ATT_SMEM>>>(Qhi, Qlo, Khi, Klo, VThi, VTlo, As);

    dim3 ogrid(EMB / 128, MROWS / 128);
    gemm_mma_kernel<<<ogrid, 256, G_SMEM>>>(As, Ws + 3 * (size_t)EMB * K3, b_o, nullptr, nullptr,
                                            nullptr, nullptr, nullptr, nullptr, nullptr, nullptr,
                                            out, 1);
}

// round 7
// speedup vs baseline: 2.9315x; 1.0635x over previous
#include <cuda_runtime.h>
#include <cuda_bf16.h>
#include <stdint.h>
#include <math.h>

#define BATCH   2
#define SEQ     2048
#define EMB     1024
#define NHEAD   16
#define HDIM    64
#define MROWS   (BATCH * SEQ)
#define K3      (3 * EMB)
#define QKV_ELEMS (BATCH * NHEAD * SEQ * HDIM)

// Scratch (__device__ globals)
__device__ __nv_bfloat16 g_Qhi[QKV_ELEMS];
__device__ __nv_bfloat16 g_Qlo[QKV_ELEMS];
__device__ __nv_bfloat16 g_Khi[QKV_ELEMS];
__device__ __nv_bfloat16 g_Klo[QKV_ELEMS];
__device__ __nv_bfloat16 g_Vhi[QKV_ELEMS];
__device__ __nv_bfloat16 g_Vlo[QKV_ELEMS];
__device__ __nv_bfloat16 g_VThi[QKV_ELEMS];   // [B,H,D,S]
__device__ __nv_bfloat16 g_VTlo[QKV_ELEMS];
__device__ __nv_bfloat16 g_Xs[(size_t)MROWS * K3];
__device__ __nv_bfloat16 g_Ws[4][(size_t)EMB * K3];
__device__ __nv_bfloat16 g_As[(size_t)MROWS * K3];

// ---------------------------------------------------------------------------
__device__ __forceinline__ uint32_t smem_u32(const void* p) {
    uint32_t a;
    asm("{ .reg .u64 t; cvta.to.shared.u64 t, %1; cvt.u32.u64 %0, t; }" : "=r"(a) : "l"(p));
    return a;
}
#define CP_ASYNC16(dst, src) asm volatile("cp.async.cg.shared.global [%0], [%1], 16;" :: "r"(dst), "l"(src))
#define CP_COMMIT()  asm volatile("cp.async.commit_group;" ::: "memory")
#define CP_WAIT2()   asm volatile("cp.async.wait_group 2;" ::: "memory")
#define CP_WAIT1()   asm volatile("cp.async.wait_group 1;" ::: "memory")
#define CP_WAIT0()   asm volatile("cp.async.wait_group 0;" ::: "memory")

__device__ __forceinline__ void ldsm_x4(uint32_t& r0, uint32_t& r1, uint32_t& r2, uint32_t& r3,
                                        uint32_t addr)
{
    asm volatile("ldmatrix.sync.aligned.m8n8.x4.shared.b16 {%0,%1,%2,%3}, [%4];"
        : "=r"(r0), "=r"(r1), "=r"(r2), "=r"(r3) : "r"(addr));
}

__device__ __forceinline__ void hilo2(float x, float y, uint32_t& hi, uint32_t& lo)
{
    __nv_bfloat16 hx = __float2bfloat16(x), hy = __float2bfloat16(y);
    __nv_bfloat16 lx = __float2bfloat16(x - __bfloat162float(hx));
    __nv_bfloat16 ly = __float2bfloat16(y - __bfloat162float(hy));
    __nv_bfloat162 h2; h2.x = hx; h2.y = hy;
    __nv_bfloat162 l2; l2.x = lx; l2.y = ly;
    hi = *(uint32_t*)&h2;
    lo = *(uint32_t*)&l2;
}

__device__ __forceinline__ void mma16816(float* c, const uint32_t* a, const uint32_t* b)
{
    asm volatile(
        "mma.sync.aligned.m16n8k16.row.col.f32.bf16.bf16.f32 "
        "{%0,%1,%2,%3}, {%4,%5,%6,%7}, {%8,%9}, {%0,%1,%2,%3};"
        : "+f"(c[0]), "+f"(c[1]), "+f"(c[2]), "+f"(c[3])
        : "r"(a[0]), "r"(a[1]), "r"(a[2]), "r"(a[3]), "r"(b[0]), "r"(b[1]));
}

// ---------------------------------------------------------------------------
// Split conversion kernels
// ---------------------------------------------------------------------------
__global__ void split_x_kernel(const float* __restrict__ in,
                               __nv_bfloat16* __restrict__ out)
{
    int idx = blockIdx.x * blockDim.x + threadIdx.x;
    int r = idx >> 10;
    int k = idx & 1023;
    float x = in[idx];
    __nv_bfloat16 hi = __float2bfloat16(x);
    __nv_bfloat16 lo = __float2bfloat16(x - __bfloat162float(hi));
    __nv_bfloat16* o = out + (size_t)r * K3 + k;
    o[0] = hi; o[1024] = hi; o[2048] = lo;
}

__global__ void split_w_kernel(const float* __restrict__ W0, const float* __restrict__ W1,
                               const float* __restrict__ W2, const float* __restrict__ W3,
                               __nv_bfloat16* __restrict__ out)
{
    int w = blockIdx.y;
    const float* in = (w == 0) ? W0 : (w == 1) ? W1 : (w == 2) ? W2 : W3;
    int idx = blockIdx.x * blockDim.x + threadIdx.x;
    int r = idx >> 10;
    int k = idx & 1023;
    float x = in[idx];
    __nv_bfloat16 hi = __float2bfloat16(x);
    __nv_bfloat16 lo = __float2bfloat16(x - __bfloat162float(hi));
    __nv_bfloat16* o = out + (size_t)w * EMB * K3 + (size_t)r * K3 + k;
    o[0] = hi; o[1024] = lo; o[2048] = hi;
}

// ---------------------------------------------------------------------------
// V transpose: [B,H,S,D] -> [B,H,D,S]
// ---------------------------------------------------------------------------
__global__ void __launch_bounds__(256)
transpose_v_kernel(const __nv_bfloat16* __restrict__ Vhi, const __nv_bfloat16* __restrict__ Vlo,
                   __nv_bfloat16* __restrict__ VThi, __nv_bfloat16* __restrict__ VTlo)
{
    __shared__ __nv_bfloat16 t0[64][72];
    __shared__ __nv_bfloat16 t1[64][72];
    const int tid = threadIdx.x;
    const int st  = blockIdx.x * 64;
    const int bh  = blockIdx.y;
    const size_t bi = (size_t)bh * SEQ * HDIM;
    const size_t bo = (size_t)bh * HDIM * SEQ;

#pragma unroll
    for (int j = 0; j < 2; j++) {
        int id  = tid + j * 256;
        int row = id >> 3;
        int co  = (id & 7) * 8;
        *(uint4*)&t0[row][co] = *(const uint4*)&Vhi[bi + (size_t)(st + row) * HDIM + co];
        *(uint4*)&t1[row][co] = *(const uint4*)&Vlo[bi + (size_t)(st + row) * HDIM + co];
    }
    __syncthreads();

#pragma unroll
    for (int j = 0; j < 2; j++) {
        int id  = tid + j * 256;
        int d   = id >> 3;
        int co  = (id & 7) * 8;
        __nv_bfloat16 h[8], l[8];
#pragma unroll
        for (int e = 0; e < 8; e++) { h[e] = t0[co + e][d]; l[e] = t1[co + e][d]; }
        *(uint4*)&VThi[bo + (size_t)d * SEQ + st + co] = *(uint4*)h;
        *(uint4*)&VTlo[bo + (size_t)d * SEQ + st + co] = *(uint4*)l;
    }
}

// ---------------------------------------------------------------------------
// bf16 HMMA GEMM, K=3072, 128x128 tile, 8 warps, 3-stage cp.async, ldmatrix.
// ---------------------------------------------------------------------------
#define GPAD   40
#define KCH    32
#define NCHUNK (K3 / KCH)
#define G_SMEM (2 * 3 * 128 * GPAD * 2)

__global__ void __launch_bounds__(256, 2)
gemm_mma_kernel(const __nv_bfloat16* __restrict__ A,
                const __nv_bfloat16* __restrict__ B,
                const float* __restrict__ bias0, const float* __restrict__ bias1,
                const float* __restrict__ bias2,
                __nv_bfloat16* __restrict__ Qhi, __nv_bfloat16* __restrict__ Qlo,
                __nv_bfloat16* __restrict__ Khi, __nv_bfloat16* __restrict__ Klo,
                __nv_bfloat16* __restrict__ Vhi, __nv_bfloat16* __restrict__ Vlo,
                float* __restrict__ Cf, int mode)
{
    extern __shared__ __nv_bfloat16 smraw[];
    __nv_bfloat16 (*As)[128][GPAD] = reinterpret_cast<__nv_bfloat16(*)[128][GPAD]>(smraw);
    __nv_bfloat16 (*Bs)[128][GPAD] = reinterpret_cast<__nv_bfloat16(*)[128][GPAD]>(smraw + 3 * 128 * GPAD);

    const int tid  = threadIdx.x;
    const int wid  = tid >> 5;
    const int lane = tid & 31;
    const int g    = lane >> 2;
    const int t    = lane & 3;
    const int bm   = blockIdx.y;
    const int bn   = blockIdx.x;
    const int wm   = (wid >> 2) * 64;
    const int wn   = (wid & 3) * 32;

    // ldmatrix lane offsets
    const int arow = (lane & 7) + ((lane >> 3) & 1) * 8;
    const int acol = (lane >> 4) * 8;
    const int brow = (lane & 7) + ((lane >> 4) & 1) * 8;
    const int bcol = ((lane >> 3) & 1) * 8;

    const int lrow = tid >> 1;
    const int lco  = (tid & 1) * 16;
    const __nv_bfloat16* Ag = A + (size_t)(bm * 128 + lrow) * K3 + lco;
    const __nv_bfloat16* Bg = B + (size_t)(bn * 128 + lrow) * K3 + lco;
    const uint32_t dA = smem_u32(&As[0][lrow][lco]);
    const uint32_t dB = smem_u32(&Bs[0][lrow][lco]);
    const uint32_t stg_bytes = 128 * GPAD * 2;

    const uint32_t aBase = smem_u32(&As[0][0][0]);
    const uint32_t bBase = smem_u32(&Bs[0][0][0]);

    auto load_st = [&](int st, int k0) {
        CP_ASYNC16(dA + st * stg_bytes,      Ag + k0);
        CP_ASYNC16(dA + st * stg_bytes + 16, Ag + k0 + 8);
        CP_ASYNC16(dB + st * stg_bytes,      Bg + k0);
        CP_ASYNC16(dB + st * stg_bytes + 16, Bg + k0 + 8);
        CP_COMMIT();
    };

    float acc[4][4][4];
#pragma unroll
    for (int i = 0; i < 4; i++)
#pragma unroll
        for (int j = 0; j < 4; j++)
#pragma unroll
            for (int q = 0; q < 4; q++) acc[i][j][q] = 0.f;

    load_st(0, 0);
    load_st(1, KCH);

    for (int c = 0; c < NCHUNK; c++) {
        const int st = c % 3;
        if (c + 2 < NCHUNK) { load_st((c + 2) % 3, (c + 2) * KCH); CP_WAIT2(); }
        else if (c + 1 < NCHUNK) { CP_WAIT1(); }
        else { CP_WAIT0(); }
        __syncthreads();

        const uint32_t aS = aBase + st * stg_bytes;
        const uint32_t bS = bBase + st * stg_bytes;

#pragma unroll
        for (int kk = 0; kk < KCH; kk += 16) {
            uint32_t af[4][4], bf[4][2];
#pragma unroll
            for (int mi = 0; mi < 4; mi++) {
                uint32_t addr = aS + (((uint32_t)(wm + mi * 16 + arow)) * GPAD + kk + acol) * 2;
                ldsm_x4(af[mi][0], af[mi][1], af[mi][2], af[mi][3], addr);
            }
#pragma unroll
            for (int np = 0; np < 2; np++) {
                uint32_t addr = bS + (((uint32_t)(wn + np * 16 + brow)) * GPAD + kk + bcol) * 2;
                ldsm_x4(bf[2 * np][0], bf[2 * np][1], bf[2 * np + 1][0], bf[2 * np + 1][1], addr);
            }
#pragma unroll
            for (int mi = 0; mi < 4; mi++)
#pragma unroll
                for (int ni = 0; ni < 4; ni++)
                    mma16816(acc[mi][ni], af[mi], bf[ni]);
        }
        __syncthreads();
    }

#pragma unroll
    for (int mi = 0; mi < 4; mi++) {
        const int r0 = bm * 128 + wm + mi * 16 + g;
#pragma unroll
        for (int ni = 0; ni < 4; ni++) {
            const int c = bn * 128 + wn + ni * 8 + 2 * t;
            if (mode == 0) {
                const int which = c >> 10;
                const int cc    = c & 1023;
                const float* bp = (which == 0) ? bias0 : (which == 1) ? bias1 : bias2;
                const float bv0 = bp[cc], bv1 = bp[cc + 1];
                float v00 = acc[mi][ni][0] + bv0, v01 = acc[mi][ni][1] + bv1;
                float v10 = acc[mi][ni][2] + bv0, v11 = acc[mi][ni][3] + bv1;
                const int b = r0 >> 11, sq = r0 & 2047;
                const int h = cc >> 6, d = cc & 63;
                size_t off0 = (((size_t)(b * NHEAD + h) * SEQ) + sq) * HDIM + d;
                size_t off1 = off0 + 8 * HDIM;
                __nv_bfloat16* Hh = (which == 0) ? Qhi : (which == 1) ? Khi : Vhi;
                __nv_bfloat16* Ll = (which == 0) ? Qlo : (which == 1) ? Klo : Vlo;
                uint32_t hi0, lo0, hi1, lo1;
                hilo2(v00, v01, hi0, lo0);
                hilo2(v10, v11, hi1, lo1);
                *(uint32_t*)(Hh + off0) = hi0;
                *(uint32_t*)(Ll + off0) = lo0;
                *(uint32_t*)(Hh + off1) = hi1;
                *(uint32_t*)(Ll + off1) = lo1;
            } else {
                const float bv0 = bias0[c], bv1 = bias0[c + 1];
                *(float2*)(Cf + (size_t)r0 * EMB + c) =
                    make_float2(acc[mi][ni][0] + bv0, acc[mi][ni][1] + bv1);
                *(float2*)(Cf + (size_t)(r0 + 8) * EMB + c) =
                    make_float2(acc[mi][ni][2] + bv0, acc[mi][ni][3] + bv1);
            }
        }
    }
}

// ---------------------------------------------------------------------------
// Tensor-core flash attention: cp.async double-buffer + ldmatrix frags.
// ---------------------------------------------------------------------------
#define ASTR 72
#define A_STG (64 * ASTR)
#define ATT_SMEM (8 * A_STG * 2)

__global__ void __launch_bounds__(128, 3)
attn_mma_kernel(const __nv_bfloat16* __restrict__ Qhi, const __nv_bfloat16* __restrict__ Qlo,
                const __nv_bfloat16* __restrict__ Khi, const __nv_bfloat16* __restrict__ Klo,
                const __nv_bfloat16* __restrict__ VThi, const __nv_bfloat16* __restrict__ VTlo,
                __nv_bfloat16* __restrict__ Out)
{
    extern __shared__ __nv_bfloat16 sm[];
    __nv_bfloat16* sK  = sm;
    __nv_bfloat16* sVT = sm + 4 * A_STG;

    const int tid  = threadIdx.x;
    const int wid  = tid >> 5;
    const int lane = tid & 31;
    const int g    = lane >> 2;
    const int t    = lane & 3;
    const int qt   = blockIdx.x;
    const int bh   = blockIdx.y;
    const size_t base  = (size_t)bh * SEQ * HDIM;
    const size_t baseT = (size_t)bh * HDIM * SEQ;

    // ldmatrix lane offsets (B-pair pattern)
    const int brow = (lane & 7) + ((lane >> 4) & 1) * 8;
    const int bcol = ((lane >> 3) & 1) * 8;

    // --- Stage Q tile into sK stage 0, extract frags ---
#pragma unroll
    for (int i = 0; i < 4; i++) {
        int idx = tid + 128 * i;
        int row = idx >> 3;
        int co  = (idx & 7) * 8;
        *(uint4*)&sK[row * ASTR + co]         = *(const uint4*)&Qhi[base + (size_t)(qt * 64 + row) * HDIM + co];
        *(uint4*)&sK[A_STG + row * ASTR + co] = *(const uint4*)&Qlo[base + (size_t)(qt * 64 + row) * HDIM + co];
    }
    __syncthreads();

    uint32_t qh[4][4], ql[4][4];
    {
        // A-frag ldmatrix lane offsets
        const int arow = (lane & 7) + ((lane >> 3) & 1) * 8;
        const int acol = (lane >> 4) * 8;
        const uint32_t qBase = smem_u32(sK);
#pragma unroll
        for (int kj = 0; kj < 4; kj++) {
            uint32_t ah = qBase + (((uint32_t)(wid * 16 + arow)) * ASTR + 16 * kj + acol) * 2;
            ldsm_x4(qh[kj][0], qh[kj][1], qh[kj][2], qh[kj][3], ah);
            ldsm_x4(ql[kj][0], ql[kj][1], ql[kj][2], ql[kj][3], ah + A_STG * 2);
        }
    }
    __syncthreads();

    const uint32_t sKa  = smem_u32(sK);
    const uint32_t sVTa = smem_u32(sVT);
    auto stage = [&](int st, int kt) {
#pragma unroll
        for (int j = 0; j < 4; j++) {
            int id  = tid + 128 * j;
            int row = id >> 3;
            int co  = (id & 7) * 8;
            uint32_t so = ((uint32_t)row * ASTR + co) * 2;
            CP_ASYNC16(sKa  + (st * 2 + 0) * A_STG * 2 + so, Khi  + base  + (size_t)(kt + row) * HDIM + co);
            CP_ASYNC16(sKa  + (st * 2 + 1) * A_STG * 2 + so, Klo  + base  + (size_t)(kt + row) * HDIM + co);
            CP_ASYNC16(sVTa + (st * 2 + 0) * A_STG * 2 + so, VThi + baseT + (size_t)row * SEQ + kt + co);
            CP_ASYNC16(sVTa + (st * 2 + 1) * A_STG * 2 + so, VTlo + baseT + (size_t)row * SEQ + kt + co);
        }
        CP_COMMIT();
    };

    float o[8][4];
#pragma unroll
    for (int ni = 0; ni < 8; ni++)
#pragma unroll
        for (int j = 0; j < 4; j++) o[ni][j] = 0.f;
    float m0 = -1e30f, m1 = -1e30f, l0 = 0.f, l1 = 0.f;

    stage(0, 0);
    stage(1, 64);

    const int NT = SEQ / 64;
    for (int it = 0; it < NT; it++) {
        const int s = it & 1;
        if (it + 1 < NT) { CP_WAIT1(); } else { CP_WAIT0(); }
        __syncthreads();

        const uint32_t cKhiA = sKa  + (s * 2 + 0) * A_STG * 2;
        const uint32_t cKloA = sKa  + (s * 2 + 1) * A_STG * 2;
        const uint32_t cVhiA = sVTa + (s * 2 + 0) * A_STG * 2;
        const uint32_t cVloA = sVTa + (s * 2 + 1) * A_STG * 2;
        const uint32_t bOff  = ((uint32_t)brow * ASTR + bcol) * 2;

        // --- S = Q K^T (3 split terms) ---
        float sc[8][4];
#pragma unroll
        for (int ni = 0; ni < 8; ni++)
#pragma unroll
            for (int j = 0; j < 4; j++) sc[ni][j] = 0.f;

#pragma unroll
        for (int kj = 0; kj < 4; kj++) {
#pragma unroll
            for (int np = 0; np < 4; np++) {
                uint32_t off = bOff + ((uint32_t)np * 16 * ASTR + 16 * kj) * 2;
                uint32_t h0[2], h1[2], l0_[2], l1_[2];
                ldsm_x4(h0[0], h0[1], h1[0], h1[1], cKhiA + off);
                ldsm_x4(l0_[0], l0_[1], l1_[0], l1_[1], cKloA + off);
                mma16816(sc[2 * np],     qh[kj], h0);
                mma16816(sc[2 * np],     qh[kj], l0_);
                mma16816(sc[2 * np],     ql[kj], h0);
                mma16816(sc[2 * np + 1], qh[kj], h1);
                mma16816(sc[2 * np + 1], qh[kj], l1_);
                mma16816(sc[2 * np + 1], ql[kj], h1);
            }
        }

        // --- online softmax ---
        float mx0 = -1e30f, mx1 = -1e30f;
#pragma unroll
        for (int ni = 0; ni < 8; ni++) {
            sc[ni][0] *= 0.125f; sc[ni][1] *= 0.125f;
            sc[ni][2] *= 0.125f; sc[ni][3] *= 0.125f;
            mx0 = fmaxf(mx0, fmaxf(sc[ni][0], sc[ni][1]));
            mx1 = fmaxf(mx1, fmaxf(sc[ni][2], sc[ni][3]));
        }
        mx0 = fmaxf(mx0, __shfl_xor_sync(0xffffffff, mx0, 1));
        mx0 = fmaxf(mx0, __shfl_xor_sync(0xffffffff, mx0, 2));
        mx1 = fmaxf(mx1, __shfl_xor_sync(0xffffffff, mx1, 1));
        mx1 = fmaxf(mx1, __shfl_xor_sync(0xffffffff, mx1, 2));

        const float nm0 = fmaxf(m0, mx0);
        const float nm1 = fmaxf(m1, mx1);
        const float rs0 = __expf(m0 - nm0);
        const float rs1 = __expf(m1 - nm1);
        m0 = nm0; m1 = nm1;
        l0 *= rs0; l1 *= rs1;
#pragma unroll
        for (int ni = 0; ni < 8; ni++) {
            o[ni][0] *= rs0; o[ni][1] *= rs0;
            o[ni][2] *= rs1; o[ni][3] *= rs1;
            sc[ni][0] = __expf(sc[ni][0] - m0);
            sc[ni][1] = __expf(sc[ni][1] - m0);
            sc[ni][2] = __expf(sc[ni][2] - m1);
            sc[ni][3] = __expf(sc[ni][3] - m1);
            l0 += sc[ni][0] + sc[ni][1];
            l1 += sc[ni][2] + sc[ni][3];
        }

        // --- O += P V (3 split terms) ---
#pragma unroll
        for (int kj = 0; kj < 4; kj++) {
            uint32_t ah[4], al[4];
            hilo2(sc[2 * kj][0],     sc[2 * kj][1],     ah[0], al[0]);
            hilo2(sc[2 * kj][2],     sc[2 * kj][3],     ah[1], al[1]);
            hilo2(sc[2 * kj + 1][0], sc[2 * kj + 1][1], ah[2], al[2]);
            hilo2(sc[2 * kj + 1][2], sc[2 * kj + 1][3], ah[3], al[3]);
#pragma unroll
            for (int np = 0; np < 4; np++) {
                uint32_t off = bOff + ((uint32_t)np * 16 * ASTR + 16 * kj) * 2;
                uint32_t h0[2], h1[2], l0_[2], l1_[2];
                ldsm_x4(h0[0], h0[1], h1[0], h1[1], cVhiA + off);
                ldsm_x4(l0_[0], l0_[1], l1_[0], l1_[1], cVloA + off);
                mma16816(o[2 * np],     ah, h0);
                mma16816(o[2 * np],     ah, l0_);
                mma16816(o[2 * np],     al, h0);
                mma16816(o[2 * np + 1], ah, h1);
                mma16816(o[2 * np + 1], ah, l1_);
                mma16816(o[2 * np + 1], al, h1);
            }
        }

        __syncthreads();
        if (it + 2 < NT) stage(s, (it + 2) * 64);
    }

    // --- finalize ---
    l0 += __shfl_xor_sync(0xffffffff, l0, 1);
    l0 += __shfl_xor_sync(0xffffffff, l0, 2);
    l1 += __shfl_xor_sync(0xffffffff, l1, 1);
    l1 += __shfl_xor_sync(0xffffffff, l1, 2);
    const float inv0 = 1.f / l0;
    const float inv1 = 1.f / l1;

    const int s0 = qt * 64 + wid * 16 + g;
    const int b  = bh >> 4;
    const int h  = bh & 15;
    const size_t row0 = (size_t)(b * SEQ + s0) * K3;
    const size_t row1 = row0 + (size_t)8 * K3;

#pragma unroll
    for (int ni = 0; ni < 8; ni++) {
        const int col = h * 64 + 8 * ni + 2 * t;
        uint32_t hi0, lo0, hi1, lo1;
        hilo2(o[ni][0] * inv0, o[ni][1] * inv0, hi0, lo0);
        hilo2(o[ni][2] * inv1, o[ni][3] * inv1, hi1, lo1);
        *(uint32_t*)&Out[row0 + col]        = hi0;
        *(uint32_t*)&Out[row0 + col + 1024] = hi0;
        *(uint32_t*)&Out[row0 + col + 2048] = lo0;
        *(uint32_t*)&Out[row1 + col]        = hi1;
        *(uint32_t*)&Out[row1 + col + 1024] = hi1;
        *(uint32_t*)&Out[row1 + col + 2048] = lo1;
    }
}

// ---------------------------------------------------------------------------
extern "C" void kernel_launch(void* const* d_in, const int* in_sizes, int n_in,
                              void* d_out, int out_size)
{
    const float* X   = (const float*)d_in[0];
    const float* W_q = (const float*)d_in[1];
    const float* b_q = (const float*)d_in[2];
    const float* W_k = (const float*)d_in[3];
    const float* b_k = (const float*)d_in[4];
    const float* W_v = (const float*)d_in[5];
    const float* b_v = (const float*)d_in[6];
    const float* W_o = (const float*)d_in[7];
    const float* b_o = (const float*)d_in[8];
    float* out = (float*)d_out;

    __nv_bfloat16 *Qhi, *Qlo, *Khi, *Klo, *Vhi, *Vlo, *VThi, *VTlo, *Xs, *Ws, *As;
    cudaGetSymbolAddress((void**)&Qhi, g_Qhi);
    cudaGetSymbolAddress((void**)&Qlo, g_Qlo);
    cudaGetSymbolAddress((void**)&Khi, g_Khi);
    cudaGetSymbolAddress((void**)&Klo, g_Klo);
    cudaGetSymbolAddress((void**)&Vhi, g_Vhi);
    cudaGetSymbolAddress((void**)&Vlo, g_Vlo);
    cudaGetSymbolAddress((void**)&VThi, g_VThi);
    cudaGetSymbolAddress((void**)&VTlo, g_VTlo);
    cudaGetSymbolAddress((void**)&Xs, g_Xs);
    cudaGetSymbolAddress((void**)&Ws, g_Ws);
    cudaGetSymbolAddress((void**)&As, g_As);

    cudaFuncSetAttribute(gemm_mma_kernel, cudaFuncAttributeMaxDynamicSharedMemorySize, G_SMEM);
    cudaFuncSetAttribute(attn_mma_kernel, cudaFuncAttributeMaxDynamicSharedMemorySize, ATT_SMEM);

    const int cthr = 256;
    split_x_kernel<<<MROWS * EMB / cthr, cthr>>>(X, Xs);
    dim3 wgrid(EMB * EMB / cthr, 4);
    split_w_kernel<<<wgrid, cthr>>>(W_q, W_k, W_v, W_o, Ws);

    dim3 qkvgrid(K3 / 128, MROWS / 128);
    gemm_mma_kernel<<<qkvgrid, 256, G_SMEM>>>(Xs, Ws, b_q, b_k, b_v,
                                              Qhi, Qlo, Khi, Klo, Vhi, Vlo, nullptr, 0);

    dim3 tgrid(SEQ / 64, BATCH * NHEAD);
    transpose_v_kernel<<<tgrid, 256>>>(Vhi, Vlo, VThi, VTlo);

    dim3 agrid(SEQ / 64, BATCH * NHEAD);
    attn_mma_kernel<<<agrid, 128, ATT_SMEM>>>(Qhi, Qlo, Khi, Klo, VThi, VTlo, As);

    dim3 ogrid(EMB / 128, MROWS / 128);
    gemm_mma_kernel<<<ogrid, 256, G_SMEM>>>(As, Ws + 3 * (size_t)EMB * K3, b_o, nullptr, nullptr,
                                            nullptr, nullptr, nullptr, nullptr, nullptr, nullptr,
                                            out, 1);
}